// round 9
// baseline (speedup 1.0000x reference)
#include <cuda_runtime.h>
#include <cuda_bf16.h>
#include <cuda_fp16.h>
#include <cstdint>

#define SCALE_ 0.125f   // 1/sqrt(64)

// GEMM operands: fp16 pairs (u32 = 2 fp16 along k) + e4m3 quads (u32 = 4 e4m3 along k)
__device__ uint32_t g_xhp [4096*512], g_xe4h[4096*256], g_xe4l[4096*256];
__device__ uint32_t g_wqhp[512*3072], g_wqe4h[256*3072], g_wqe4l[256*3072];
__device__ float    g_of32[4096*1024];
__device__ uint32_t g_ohp [4096*512], g_oe4h[4096*256], g_oe4l[4096*256];
__device__ uint32_t g_wohp[512*1024], g_woe4h[256*1024], g_woe4l[256*1024];

// attention operands, packed bf16x2 hi/lo (validated)
__device__ uint32_t g_qh [32*2048*32], g_ql [32*2048*32]; // Q  [bh][l][dk2]
__device__ uint32_t g_kh [32*32*2048], g_kl [32*32*2048]; // K  [bh][dk2][l]
__device__ uint32_t g_vth[32*2048*32], g_vtl[32*2048*32]; // Vt [bh][l][dk2]
__device__ uint32_t g_vh [32*1024*64], g_vl [32*1024*64]; // V  [bh][l2][dk]
__device__ uint32_t g_mb [2*2048*64];                     // mask bits

// ---------------------------------------------------------------------------
// Helpers
// ---------------------------------------------------------------------------
__device__ __forceinline__ uint32_t pack_hl(float a, float b, uint32_t& lo) {
    __nv_bfloat162 t, u;
    t.x = __float2bfloat16_rn(a);
    t.y = __float2bfloat16_rn(b);
    u.x = __float2bfloat16_rn(a - __bfloat162float(t.x));
    u.y = __float2bfloat16_rn(b - __bfloat162float(t.y));
    lo = *reinterpret_cast<uint32_t*>(&u);
    return *reinterpret_cast<uint32_t*>(&t);
}
__device__ __forceinline__ uint32_t pack_h2(float a, float b) {
    __half2 h = __floats2half2_rn(a, b);
    return *reinterpret_cast<uint32_t*>(&h);
}
__device__ __forceinline__ uint32_t pack_e4(float v0, float v1, float v2, float v3) {
    uint16_t w01, w23;
    asm("cvt.rn.satfinite.e4m3x2.f32 %0, %1, %2;" : "=h"(w01) : "f"(v1), "f"(v0));
    asm("cvt.rn.satfinite.e4m3x2.f32 %0, %1, %2;" : "=h"(w23) : "f"(v3), "f"(v2));
    return (uint32_t)w01 | ((uint32_t)w23 << 16);
}
__device__ __forceinline__ void cp16(uint32_t saddr, const void* gptr) {
    asm volatile("cp.async.cg.shared.global [%0], [%1], 16;\n" :: "r"(saddr), "l"(gptr));
}
__device__ __forceinline__ void cp_commit() {
    asm volatile("cp.async.commit_group;\n" ::: "memory");
}
__device__ __forceinline__ void mma16816(float* c, const uint32_t* a, const uint32_t* b) {
    asm volatile(
        "mma.sync.aligned.m16n8k16.row.col.f32.bf16.bf16.f32 "
        "{%0,%1,%2,%3}, {%4,%5,%6,%7}, {%8,%9}, {%0,%1,%2,%3};\n"
        : "+f"(c[0]), "+f"(c[1]), "+f"(c[2]), "+f"(c[3])
        : "r"(a[0]), "r"(a[1]), "r"(a[2]), "r"(a[3]), "r"(b[0]), "r"(b[1]));
}
__device__ __forceinline__ void mma_f16(float* c, const uint32_t* a, const uint32_t* b) {
    asm volatile(
        "mma.sync.aligned.m16n8k16.row.col.f32.f16.f16.f32 "
        "{%0,%1,%2,%3}, {%4,%5,%6,%7}, {%8,%9}, {%0,%1,%2,%3};\n"
        : "+f"(c[0]), "+f"(c[1]), "+f"(c[2]), "+f"(c[3])
        : "r"(a[0]), "r"(a[1]), "r"(a[2]), "r"(a[3]), "r"(b[0]), "r"(b[1]));
}
__device__ __forceinline__ void mma_e4(float* c, const uint32_t* a, const uint32_t* b) {
    asm volatile(
        "mma.sync.aligned.m16n8k32.row.col.f32.e4m3.e4m3.f32 "
        "{%0,%1,%2,%3}, {%4,%5,%6,%7}, {%8,%9}, {%0,%1,%2,%3};\n"
        : "+f"(c[0]), "+f"(c[1]), "+f"(c[2]), "+f"(c[3])
        : "r"(a[0]), "r"(a[1]), "r"(a[2]), "r"(a[3]), "r"(b[0]), "r"(b[1]));
}

// ---------------------------------------------------------------------------
// Operand prep kernels
// ---------------------------------------------------------------------------
__global__ void split_ax(const float* __restrict__ in, uint32_t* __restrict__ hp,
                         uint32_t* __restrict__ e4h, uint32_t* __restrict__ e4l, int n4)
{
    int i = blockIdx.x * 256 + threadIdx.x;
    if (i >= n4) return;
    float4 v = ((const float4*)in)[i];
    uint32_t h0 = pack_h2(v.x, v.y), h1 = pack_h2(v.z, v.w);
    hp[2*i] = h0; hp[2*i+1] = h1;
    __half2 H0 = *reinterpret_cast<__half2*>(&h0);
    __half2 H1 = *reinterpret_cast<__half2*>(&h1);
    float r0 = (v.x - __half2float(H0.x)) * 2048.f;
    float r1 = (v.y - __half2float(H0.y)) * 2048.f;
    float r2 = (v.z - __half2float(H1.x)) * 2048.f;
    float r3 = (v.w - __half2float(H1.y)) * 2048.f;
    e4h[i] = pack_e4(v.x, v.y, v.z, v.w);
    e4l[i] = pack_e4(r0, r1, r2, r3);
}

__global__ void split_w(const float* __restrict__ in, uint32_t* __restrict__ hp,
                        uint32_t* __restrict__ e4h, uint32_t* __restrict__ e4l, int N)
{
    int n  = blockIdx.x * blockDim.x + threadIdx.x;
    int k4 = blockIdx.y;
    float v0 = in[(size_t)(4*k4+0)*N + n];
    float v1 = in[(size_t)(4*k4+1)*N + n];
    float v2 = in[(size_t)(4*k4+2)*N + n];
    float v3 = in[(size_t)(4*k4+3)*N + n];
    uint32_t h0 = pack_h2(v0, v1), h1 = pack_h2(v2, v3);
    hp[(size_t)(2*k4)*N + n]   = h0;
    hp[(size_t)(2*k4+1)*N + n] = h1;
    __half2 H0 = *reinterpret_cast<__half2*>(&h0);
    __half2 H1 = *reinterpret_cast<__half2*>(&h1);
    float r0 = (v0 - __half2float(H0.x)) * 2048.f;
    float r1 = (v1 - __half2float(H0.y)) * 2048.f;
    float r2 = (v2 - __half2float(H1.x)) * 2048.f;
    float r3 = (v3 - __half2float(H1.y)) * 2048.f;
    e4h[(size_t)k4*N + n] = pack_e4(v0, v1, v2, v3);
    e4l[(size_t)k4*N + n] = pack_e4(r0, r1, r2, r3);
}

__global__ void maskpack(const int* __restrict__ mask)
{
    int idx = blockIdx.x * 256 + threadIdx.x;
    int w   = idx & 63;
    int row = idx >> 6;
    const int4* p = (const int4*)(mask + (size_t)row * 2048 + w * 32);
    uint32_t bits = 0;
#pragma unroll
    for (int i = 0; i < 8; i++) {
        int4 v = p[i];
        bits |= (uint32_t)(v.x != 0) << (4*i)
             |  (uint32_t)(v.y != 0) << (4*i+1)
             |  (uint32_t)(v.z != 0) << (4*i+2)
             |  (uint32_t)(v.w != 0) << (4*i+3);
    }
    g_mb[idx] = bits;
}

__global__ void vrepack()
{
    int idx = blockIdx.x * 256 + threadIdx.x;
    int d  = idx & 63;
    int l2 = (idx >> 6) & 1023;
    int bh = idx >> 16;
    const uint16_t* th = (const uint16_t*)g_vth;
    const uint16_t* tl = (const uint16_t*)g_vtl;
    size_t i0 = ((size_t)bh*2048 + 2*l2    ) * 64 + d;
    size_t i1 = ((size_t)bh*2048 + 2*l2 + 1) * 64 + d;
    g_vh[idx] = (uint32_t)th[i0] | ((uint32_t)th[i1] << 16);
    g_vl[idx] = (uint32_t)tl[i0] | ((uint32_t)tl[i1] << 16);
}

// ---------------------------------------------------------------------------
// fp16+fp8 GEMM: block 128x128, K-tile 32, 512 threads (16 warps, warp 32x32).
// Per k16: one f16 MMA (hi*hi) + one e4m3 k32 MMA (both cross terms, *2^11).
// Dual accumulators C / Cx merged in epilogue. ~120 regs -> no spills.
// ---------------------------------------------------------------------------
#define OA    0
#define OAH4  2560
#define OAL4  4096
#define OB    5632
#define OBH4  7808
#define OBL4  8896
#define STG   9984
#define GEMM_SMEM (2*STG*4)   // 79872 B

template<int EPI>
__global__ void __launch_bounds__(512, 1)
gemm_f16fp8(const uint32_t* __restrict__ Ahp, const uint32_t* __restrict__ Ae4h,
            const uint32_t* __restrict__ Ae4l,
            const uint32_t* __restrict__ Bhp, const uint32_t* __restrict__ Be4h,
            const uint32_t* __restrict__ Be4l,
            const float* __restrict__ bias, float* __restrict__ outp, int N)
{
    extern __shared__ uint32_t sm[];
    const int tid  = threadIdx.x;
    const int lane = tid & 31;
    const int wid  = tid >> 5;
    const int wm   = wid >> 2;      // 0..3 -> 32-row band
    const int wn   = wid & 3;       // 0..3 -> 32-col band
    const int c    = lane & 3;
    const int rq   = lane >> 2;
    const int m0   = blockIdx.y * 128;
    const int n0   = blockIdx.x * 128;

    const uint32_t sbase = (uint32_t)__cvta_generic_to_shared(sm);

    float C[2][4][4], Cx[2][4][4];
#pragma unroll
    for (int mt = 0; mt < 2; mt++)
#pragma unroll
        for (int nt = 0; nt < 4; nt++)
#pragma unroll
            for (int e = 0; e < 4; e++) { C[mt][nt][e] = 0.f; Cx[mt][nt][e] = 0.f; }

    auto load_stage = [&](int s, int t) {
        const uint32_t sa = sbase + (uint32_t)(s * STG) * 4;
        const int kp0 = t * 16, k40 = t * 8;
        {   // A fp16: 2048 u32 = 512 cp16
            const int row = tid >> 2, c4 = (tid & 3) << 2;
            cp16(sa + (OA + row*20 + c4)*4, Ahp + (size_t)(m0+row)*512 + kp0 + c4);
        }
        {   // A e4m3 hi/lo: 2048 u32 = 512 cp16
            const int row = tid >> 2, sel = tid & 3;
            const uint32_t* src = (sel < 2) ? Ae4h : Ae4l;
            const int off = (sel & 1) * 4;
            cp16(sa + (((sel < 2) ? OAH4 : OAL4) + row*12 + off)*4,
                 src + (size_t)(m0+row)*256 + k40 + off);
        }
        {   // B fp16: 2048 u32 = 512 cp16
            const int row = tid >> 5, c4 = (tid & 31) << 2;
            cp16(sa + (OB + row*136 + c4)*4, Bhp + (size_t)(kp0+row)*N + n0 + c4);
        }
        {   // B e4m3 hi/lo: 2048 u32 = 512 cp16
            const int sel = tid >> 8, row = (tid >> 5) & 7, c4 = (tid & 31) << 2;
            const uint32_t* src = sel ? Be4l : Be4h;
            cp16(sa + ((sel ? OBL4 : OBH4) + row*136 + c4)*4,
                 src + (size_t)(k40+row)*N + n0 + c4);
        }
        cp_commit();
    };

    load_stage(0, 0);

    const int T = 32;
    for (int t = 0; t < T; t++) {
        if (t + 1 < T) { load_stage((t+1)&1, t+1); }
        if (t + 1 < T) asm volatile("cp.async.wait_group 1;\n" ::: "memory");
        else           asm volatile("cp.async.wait_group 0;\n" ::: "memory");
        __syncthreads();

        const uint32_t* S = sm + (t & 1) * STG;
#pragma unroll
        for (int ss = 0; ss < 2; ss++) {
            uint32_t ah[2][4], a8[2][4];
#pragma unroll
            for (int mt = 0; mt < 2; mt++) {
                const int r0 = wm*32 + mt*16 + rq;
                ah[mt][0] = S[OA + r0*20     + ss*8 + c];
                ah[mt][1] = S[OA + (r0+8)*20 + ss*8 + c];
                ah[mt][2] = S[OA + r0*20     + ss*8 + c + 4];
                ah[mt][3] = S[OA + (r0+8)*20 + ss*8 + c + 4];
                a8[mt][0] = S[OAH4 + r0*12     + ss*4 + c];
                a8[mt][1] = S[OAH4 + (r0+8)*12 + ss*4 + c];
                a8[mt][2] = S[OAL4 + r0*12     + ss*4 + c];
                a8[mt][3] = S[OAL4 + (r0+8)*12 + ss*4 + c];
            }
            uint32_t bh[4][2], b8[4][2];
            const int k2  = ss*8 + c;
            const int k4r = ss*4 + c;
#pragma unroll
            for (int nt = 0; nt < 4; nt++) {
                const int col = wn*32 + nt*8 + rq;
                bh[nt][0] = S[OB + k2*136     + col];
                bh[nt][1] = S[OB + (k2+4)*136 + col];
                b8[nt][0] = S[OBL4 + k4r*136 + col];   // k' 0-15 : wl*2^11
                b8[nt][1] = S[OBH4 + k4r*136 + col];   // k' 16-31: wh
            }
#pragma unroll
            for (int mt = 0; mt < 2; mt++)
#pragma unroll
                for (int nt = 0; nt < 4; nt++)
                    mma_f16(C[mt][nt], ah[mt], bh[nt]);
#pragma unroll
            for (int mt = 0; mt < 2; mt++)
#pragma unroll
                for (int nt = 0; nt < 4; nt++)
                    mma_e4(Cx[mt][nt], a8[mt], b8[nt]);
        }
        __syncthreads();
    }

    const float INV = 1.f / 2048.f;
#pragma unroll
    for (int mt = 0; mt < 2; mt++) {
#pragma unroll
        for (int nt = 0; nt < 4; nt++) {
            const int r  = m0 + wm*32 + mt*16 + rq;
            const int cc = n0 + wn*32 + nt*8 + c*2;
            const float b0 = bias[cc], b1 = bias[cc+1];
            const float v00 = C[mt][nt][0] + Cx[mt][nt][0]*INV + b0;
            const float v01 = C[mt][nt][1] + Cx[mt][nt][1]*INV + b1;
            const float v10 = C[mt][nt][2] + Cx[mt][nt][2]*INV + b0;
            const float v11 = C[mt][nt][3] + Cx[mt][nt][3]*INV + b1;
            if (EPI == 0) {
                const int part = cc >> 10;
                const int d    = cc & 1023;
                const int h    = d >> 6;
                const int dk2  = (d & 63) >> 1;
                const int bI   = r >> 11;
                const int l    = r & 2047;
                const int bhI  = bI*16 + h;
                uint32_t lo0, lo1;
                uint32_t hi0 = pack_hl(v00, v01, lo0);
                uint32_t hi1 = pack_hl(v10, v11, lo1);
                if (part == 0) {
                    size_t i0 = ((size_t)bhI*2048 + l)*32 + dk2;
                    g_qh[i0] = hi0;        g_ql[i0] = lo0;
                    g_qh[i0 + 8*32] = hi1; g_ql[i0 + 8*32] = lo1;
                } else if (part == 1) {
                    size_t i0 = ((size_t)bhI*32 + dk2)*2048 + l;
                    g_kh[i0]     = hi0;  g_kl[i0]     = lo0;
                    g_kh[i0 + 8] = hi1;  g_kl[i0 + 8] = lo1;
                } else {
                    size_t i0 = ((size_t)bhI*2048 + l)*32 + dk2;
                    g_vth[i0] = hi0;        g_vtl[i0] = lo0;
                    g_vth[i0 + 8*32] = hi1; g_vtl[i0 + 8*32] = lo1;
                }
            } else {
                *(float2*)&outp[(size_t)r*N + cc]     = make_float2(v00, v01);
                *(float2*)&outp[(size_t)(r+8)*N + cc] = make_float2(v10, v11);
            }
        }
    }
}

// ---------------------------------------------------------------------------
// Tensor-core flash attention (bf16x3 mma.sync, validated). 128 queries/CTA.
// ---------------------------------------------------------------------------
#define AKH 0
#define AKL 2304
#define AVH 4608
#define AVL 6912
#define ASTG 9216
#define ATTN_SMEM (2*ASTG*4)   // 73728 bytes

__device__ __forceinline__ void softmax_row(float (&sC)[8][4], float (&oC)[8][4],
                                            int e0, uint32_t w0, uint32_t w1,
                                            int c, float& mi, float& li)
{
    float rm = -1e30f;
    uint32_t rbits = 0;
#pragma unroll
    for (int j = 0; j < 8; j++) {
        const uint32_t w = (j < 4) ? w0 : w1;
#pragma unroll
        for (int e = 0; e < 2; e++) {
            const int col = 8*j + 2*c + e;
            const uint32_t bit = (w >> (col & 31)) & 1u;
            const float sv = bit ? sC[j][e0+e]*SCALE_ : 0.f;
            sC[j][e0+e] = sv;
            rbits |= bit << (2*j + e);
            rm = fmaxf(rm, sv);
        }
    }
    rm = fmaxf(rm, __shfl_xor_sync(0xffffffffu, rm, 1));
    rm = fmaxf(rm, __shfl_xor_sync(0xffffffffu, rm, 2));
    const float mn  = fmaxf(mi, rm);
    const float fac = __expf(mi - mn);
    float rs = 0.f;
#pragma unroll
    for (int j = 0; j < 8; j++)
#pragma unroll
        for (int e = 0; e < 2; e++) {
            const float pd = __expf(sC[j][e0+e] - mn);
            rs += pd;
            sC[j][e0+e] = ((rbits >> (2*j + e)) & 1u) ? pd : 0.f;
        }
    rs += __shfl_xor_sync(0xffffffffu, rs, 1);
    rs += __shfl_xor_sync(0xffffffffu, rs, 2);
    li = li*fac + rs;
    mi = mn;
#pragma unroll
    for (int j = 0; j < 8; j++) { oC[j][e0] *= fac; oC[j][e0+1] *= fac; }
}

__global__ void __launch_bounds__(256, 1)
attn_mma_kernel()
{
    extern __shared__ uint32_t sm[];
    const int tid  = threadIdx.x;
    const int lane = tid & 31;
    const int wid  = tid >> 5;
    const int c    = lane & 3;
    const int rq   = lane >> 2;
    const int bh   = blockIdx.y;
    const int b    = bh >> 4;
    const int h    = bh & 15;
    const int q0   = blockIdx.x * 128;
    const int r0   = q0 + wid*16 + rq;

    const uint32_t sbase = (uint32_t)__cvta_generic_to_shared(sm);

    uint32_t qh[4][4], ql[4][4];
    {
        const uint32_t* Qh = g_qh + (size_t)bh*2048*32;
        const uint32_t* Ql = g_ql + (size_t)bh*2048*32;
#pragma unroll
        for (int t = 0; t < 4; t++) {
            qh[t][0] = Qh[(size_t)r0*32     + 8*t + c];
            qh[t][1] = Qh[(size_t)(r0+8)*32 + 8*t + c];
            qh[t][2] = Qh[(size_t)r0*32     + 8*t + c + 4];
            qh[t][3] = Qh[(size_t)(r0+8)*32 + 8*t + c + 4];
            ql[t][0] = Ql[(size_t)r0*32     + 8*t + c];
            ql[t][1] = Ql[(size_t)(r0+8)*32 + 8*t + c];
            ql[t][2] = Ql[(size_t)r0*32     + 8*t + c + 4];
            ql[t][3] = Ql[(size_t)(r0+8)*32 + 8*t + c + 4];
        }
    }

    float oC[8][4];
#pragma unroll
    for (int j = 0; j < 8; j++)
#pragma unroll
        for (int e = 0; e < 4; e++) oC[j][e] = 0.f;
    float mi[2] = {-1e30f, -1e30f};
    float li[2] = {0.f, 0.f};

    auto load_stage = [&](int s, int k0) {
        const uint32_t sa = sbase + (uint32_t)(s * ASTG) * 4;
#pragma unroll
        for (int it = 0; it < 2; it++) {
            const int idx = it*256 + tid;
            const int row = idx >> 4;
            const int c4  = (idx & 15) * 4;
            cp16(sa + (AKH + row*72 + c4)*4, g_kh + ((size_t)bh*32 + row)*2048 + k0 + c4);
            cp16(sa + (AKL + row*72 + c4)*4, g_kl + ((size_t)bh*32 + row)*2048 + k0 + c4);
            cp16(sa + (AVH + row*72 + c4)*4, g_vh + ((size_t)bh*1024 + (k0>>1) + row)*64 + c4);
            cp16(sa + (AVL + row*72 + c4)*4, g_vl + ((size_t)bh*1024 + (k0>>1) + row)*64 + c4);
        }
    };

    load_stage(0, 0);
    cp_commit();

    const uint32_t* MB = g_mb + (size_t)b*2048*64;

    for (int t32 = 0; t32 < 32; t32++) {
        const int k0 = t32 * 64;
        if (t32 + 1 < 32) { load_stage((t32+1)&1, k0 + 64); cp_commit(); }
        if (t32 + 1 < 32) asm volatile("cp.async.wait_group 1;\n" ::: "memory");
        else              asm volatile("cp.async.wait_group 0;\n" ::: "memory");
        __syncthreads();

        const uint32_t* S = sm + (t32 & 1) * ASTG;

        float sC[8][4];
#pragma unroll
        for (int j = 0; j < 8; j++)
#pragma unroll
            for (int e = 0; e < 4; e++) sC[j][e] = 0.f;

#pragma unroll
        for (int t = 0; t < 4; t++) {
#pragma unroll
            for (int jj = 0; jj < 4; jj++) {
                const int j0 = 2*jj, j1 = 2*jj + 1;
                uint32_t b0h[2], b0l[2], b1h[2], b1l[2];
                b0h[0] = S[AKH + (8*t + c)*72     + 8*j0 + rq];
                b0h[1] = S[AKH + (8*t + c + 4)*72 + 8*j0 + rq];
                b0l[0] = S[AKL + (8*t + c)*72     + 8*j0 + rq];
                b0l[1] = S[AKL + (8*t + c + 4)*72 + 8*j0 + rq];
                b1h[0] = S[AKH + (8*t + c)*72     + 8*j1 + rq];
                b1h[1] = S[AKH + (8*t + c + 4)*72 + 8*j1 + rq];
                b1l[0] = S[AKL + (8*t + c)*72     + 8*j1 + rq];
                b1l[1] = S[AKL + (8*t + c + 4)*72 + 8*j1 + rq];
                mma16816(sC[j0], qh[t], b0h);
                mma16816(sC[j1], qh[t], b1h);
                mma16816(sC[j0], qh[t], b0l);
                mma16816(sC[j1], qh[t], b1l);
                mma16816(sC[j0], ql[t], b0h);
                mma16816(sC[j1], ql[t], b1h);
            }
        }

        const int wbase = k0 >> 5;
        const uint32_t w00 = MB[(size_t)r0*64 + wbase],     w01 = MB[(size_t)r0*64 + wbase + 1];
        const uint32_t w10 = MB[(size_t)(r0+8)*64 + wbase], w11 = MB[(size_t)(r0+8)*64 + wbase + 1];
        softmax_row(sC, oC, 0, w00, w01, c, mi[0], li[0]);
        softmax_row(sC, oC, 2, w10, w11, c, mi[1], li[1]);

#pragma unroll
        for (int tp = 0; tp < 4; tp++) {
            uint32_t pah[4], pal[4];
            pah[0] = pack_hl(sC[2*tp][0],   sC[2*tp][1],   pal[0]);
            pah[1] = pack_hl(sC[2*tp][2],   sC[2*tp][3],   pal[1]);
            pah[2] = pack_hl(sC[2*tp+1][0], sC[2*tp+1][1], pal[2]);
            pah[3] = pack_hl(sC[2*tp+1][2], sC[2*tp+1][3], pal[3]);
#pragma unroll
            for (int jj = 0; jj < 4; jj++) {
                const int j0 = 2*jj, j1 = 2*jj + 1;
                uint32_t b0h[2], b0l[2], b1h[2], b1l[2];
                b0h[0] = S[AVH + (8*tp + c)*72     + 8*j0 + rq];
                b0h[1] = S[AVH + (8*tp + c + 4)*72 + 8*j0 + rq];
                b0l[0] = S[AVL + (8*tp + c)*72     + 8*j0 + rq];
                b0l[1] = S[AVL + (8*tp + c + 4)*72 + 8*j0 + rq];
                b1h[0] = S[AVH + (8*tp + c)*72     + 8*j1 + rq];
                b1h[1] = S[AVH + (8*tp + c + 4)*72 + 8*j1 + rq];
                b1l[0] = S[AVL + (8*tp + c)*72     + 8*j1 + rq];
                b1l[1] = S[AVL + (8*tp + c + 4)*72 + 8*j1 + rq];
                mma16816(oC[j0], pah, b0h);
                mma16816(oC[j1], pah, b1h);
                mma16816(oC[j0], pah, b0l);
                mma16816(oC[j1], pah, b1l);
                mma16816(oC[j0], pal, b0h);
                mma16816(oC[j1], pal, b1h);
            }
        }
        __syncthreads();
    }

    const float inv0 = 1.0f / li[0];
    const float inv1 = 1.0f / li[1];
    const size_t row0 = (size_t)b*2048 + r0;
#pragma unroll
    for (int j = 0; j < 8; j++) {
        const int cc = h*64 + 8*j + 2*c;
        *(float2*)&g_of32[row0*1024 + cc]     = make_float2(oC[j][0]*inv0, oC[j][1]*inv0);
        *(float2*)&g_of32[(row0+8)*1024 + cc] = make_float2(oC[j][2]*inv1, oC[j][3]*inv1);
    }
}

// ---------------------------------------------------------------------------

extern "C" void kernel_launch(void* const* d_in, const int* in_sizes, int n_in,
                              void* d_out, int out_size)
{
    const float* x     = (const float*)d_in[0];
    const int*   mask  = (const int*)  d_in[1];
    const float* W_qkv = (const float*)d_in[2];
    const float* b_qkv = (const float*)d_in[3];
    const float* W_out = (const float*)d_in[4];
    const float* b_out = (const float*)d_in[5];
    float* out = (float*)d_out;

    cudaFuncSetAttribute(gemm_f16fp8<0>, cudaFuncAttributeMaxDynamicSharedMemorySize, GEMM_SMEM);
    cudaFuncSetAttribute(gemm_f16fp8<1>, cudaFuncAttributeMaxDynamicSharedMemorySize, GEMM_SMEM);
    cudaFuncSetAttribute(attn_mma_kernel, cudaFuncAttributeMaxDynamicSharedMemorySize, ATTN_SMEM);

    uint32_t *xhp, *xe4h, *xe4l, *wqhp, *wqe4h, *wqe4l;
    uint32_t *ohp, *oe4h, *oe4l, *wohp, *woe4h, *woe4l;
    float* of32;
    cudaGetSymbolAddress((void**)&xhp,   g_xhp);
    cudaGetSymbolAddress((void**)&xe4h,  g_xe4h);
    cudaGetSymbolAddress((void**)&xe4l,  g_xe4l);
    cudaGetSymbolAddress((void**)&wqhp,  g_wqhp);
    cudaGetSymbolAddress((void**)&wqe4h, g_wqe4h);
    cudaGetSymbolAddress((void**)&wqe4l, g_wqe4l);
    cudaGetSymbolAddress((void**)&ohp,   g_ohp);
    cudaGetSymbolAddress((void**)&oe4h,  g_oe4h);
    cudaGetSymbolAddress((void**)&oe4l,  g_oe4l);
    cudaGetSymbolAddress((void**)&wohp,  g_wohp);
    cudaGetSymbolAddress((void**)&woe4h, g_woe4h);
    cudaGetSymbolAddress((void**)&woe4l, g_woe4l);
    cudaGetSymbolAddress((void**)&of32,  g_of32);

    // Operand prep
    split_ax<<<4096, 256>>>(x, xhp, xe4h, xe4l, 4096*256);
    split_w<<<dim3(3072/256, 256), 256>>>(W_qkv, wqhp, wqe4h, wqe4l, 3072);
    maskpack<<<(2*2048*64)/256, 256>>>(mask);

    // QKV projection (fp16 + fused-fp8 cross) -> packed bf16 Q/K/Vt
    gemm_f16fp8<0><<<dim3(24, 32), 512, GEMM_SMEM>>>(xhp, xe4h, xe4l,
                                                     wqhp, wqe4h, wqe4l,
                                                     b_qkv, nullptr, 3072);

    // V repack
    vrepack<<<(32*1024*64)/256, 256>>>();

    // Attention (bf16x3) -> g_of32
    attn_mma_kernel<<<dim3(16, 32), 256, ATTN_SMEM>>>();

    // Out-proj operand prep + GEMM
    split_ax<<<4096, 256>>>(of32, ohp, oe4h, oe4l, 4096*256);
    split_w<<<dim3(1024/256, 256), 256>>>(W_out, wohp, woe4h, woe4l, 1024);
    gemm_f16fp8<1><<<dim3(8, 32), 512, GEMM_SMEM>>>(ohp, oe4h, oe4l,
                                                    wohp, woe4h, woe4l,
                                                    b_out, out, 1024);
}

// round 10
// speedup vs baseline: 1.2865x; 1.2865x over previous
#include <cuda_runtime.h>
#include <cuda_bf16.h>
#include <cuda_fp16.h>
#include <cstdint>

#define SCALE_ 0.125f   // 1/sqrt(64)

// split-bf16 scratch for dense GEMMs (u32 = packed bf16x2)
__device__ uint32_t g_xh [4096*512], g_xl [4096*512];   // X   [M][K/2]
__device__ uint32_t g_wqh[512*3072], g_wql[512*3072];   // Wqkv[K/2][N]
__device__ uint32_t g_oh [4096*512], g_ol [4096*512];   // O   [M][K/2]  (written by attn)
__device__ uint32_t g_woh[512*1024], g_wol[512*1024];   // Wout[K/2][N]

// attention operands (f16)
__device__ uint32_t g_qh [32*2048*32], g_ql [32*2048*32]; // Q hi/lo [bh][l][dk2]
__device__ uint32_t g_kh [32*32*2048];                    // K single [bh][dk2][l]
__device__ uint32_t g_vth[32*2048*32];                    // Vt single [bh][l][dk2]
__device__ uint32_t g_vh [32*1024*64];                    // V single [bh][l2][dk]
__device__ uint32_t g_mb [2*2048*64];                     // mask bits

// ---------------------------------------------------------------------------
// Helpers
// ---------------------------------------------------------------------------
__device__ __forceinline__ uint32_t pack_hl(float a, float b, uint32_t& lo) {
    __nv_bfloat162 t, u;
    t.x = __float2bfloat16_rn(a);
    t.y = __float2bfloat16_rn(b);
    u.x = __float2bfloat16_rn(a - __bfloat162float(t.x));
    u.y = __float2bfloat16_rn(b - __bfloat162float(t.y));
    lo = *reinterpret_cast<uint32_t*>(&u);
    return *reinterpret_cast<uint32_t*>(&t);
}
__device__ __forceinline__ uint32_t pack_h2(float a, float b) {
    __half2 h = __floats2half2_rn(a, b);
    return *reinterpret_cast<uint32_t*>(&h);
}
__device__ __forceinline__ uint32_t pack_hl_f16(float a, float b, uint32_t& lo) {
    __half2 t = __floats2half2_rn(a, b);
    float ra = a - __half2float(t.x);
    float rb = b - __half2float(t.y);
    __half2 u = __floats2half2_rn(ra, rb);
    lo = *reinterpret_cast<uint32_t*>(&u);
    return *reinterpret_cast<uint32_t*>(&t);
}
__device__ __forceinline__ void cp16(uint32_t saddr, const void* gptr) {
    asm volatile("cp.async.cg.shared.global [%0], [%1], 16;\n" :: "r"(saddr), "l"(gptr));
}
__device__ __forceinline__ void cp_commit() {
    asm volatile("cp.async.commit_group;\n" ::: "memory");
}
__device__ __forceinline__ void mma16816(float* c, const uint32_t* a, const uint32_t* b) {
    asm volatile(
        "mma.sync.aligned.m16n8k16.row.col.f32.bf16.bf16.f32 "
        "{%0,%1,%2,%3}, {%4,%5,%6,%7}, {%8,%9}, {%0,%1,%2,%3};\n"
        : "+f"(c[0]), "+f"(c[1]), "+f"(c[2]), "+f"(c[3])
        : "r"(a[0]), "r"(a[1]), "r"(a[2]), "r"(a[3]), "r"(b[0]), "r"(b[1]));
}
__device__ __forceinline__ void mma_f16(float* c, const uint32_t* a, const uint32_t* b) {
    asm volatile(
        "mma.sync.aligned.m16n8k16.row.col.f32.f16.f16.f32 "
        "{%0,%1,%2,%3}, {%4,%5,%6,%7}, {%8,%9}, {%0,%1,%2,%3};\n"
        : "+f"(c[0]), "+f"(c[1]), "+f"(c[2]), "+f"(c[3])
        : "r"(a[0]), "r"(a[1]), "r"(a[2]), "r"(a[3]), "r"(b[0]), "r"(b[1]));
}

// ---------------------------------------------------------------------------
// Split conversion kernels (dense GEMM operands, bf16x3 — validated)
// ---------------------------------------------------------------------------
__global__ void split_A(const float* __restrict__ in,
                        uint32_t* __restrict__ h, uint32_t* __restrict__ l, int n)
{
    int i = blockIdx.x * blockDim.x + threadIdx.x;
    if (i >= n) return;
    float2 a = ((const float2*)in)[i];
    uint32_t lo;
    uint32_t hi = pack_hl(a.x, a.y, lo);
    h[i] = hi; l[i] = lo;
}

__global__ void split_B(const float* __restrict__ in,
                        uint32_t* __restrict__ h, uint32_t* __restrict__ l, int N)
{
    int n  = blockIdx.x * blockDim.x + threadIdx.x;
    int k2 = blockIdx.y;
    float a0 = in[(size_t)(2*k2)   * N + n];
    float a1 = in[(size_t)(2*k2+1) * N + n];
    uint32_t lo;
    uint32_t hi = pack_hl(a0, a1, lo);
    size_t o = (size_t)k2 * N + n;
    h[o] = hi; l[o] = lo;
}

__global__ void maskpack(const int* __restrict__ mask)
{
    int idx = blockIdx.x * 256 + threadIdx.x;
    int w   = idx & 63;
    int row = idx >> 6;
    const int4* p = (const int4*)(mask + (size_t)row * 2048 + w * 32);
    uint32_t bits = 0;
#pragma unroll
    for (int i = 0; i < 8; i++) {
        int4 v = p[i];
        bits |= (uint32_t)(v.x != 0) << (4*i)
             |  (uint32_t)(v.y != 0) << (4*i+1)
             |  (uint32_t)(v.z != 0) << (4*i+2)
             |  (uint32_t)(v.w != 0) << (4*i+3);
    }
    g_mb[idx] = bits;
}

// V repack: [bh][l][dk2] (pairs along dk, f16) -> [bh][l2][dk] (pairs along l)
__global__ void vrepack()
{
    int idx = blockIdx.x * 256 + threadIdx.x;
    int d  = idx & 63;
    int l2 = (idx >> 6) & 1023;
    int bh = idx >> 16;
    const uint16_t* th = (const uint16_t*)g_vth;
    size_t i0 = ((size_t)bh*2048 + 2*l2    ) * 64 + d;
    size_t i1 = ((size_t)bh*2048 + 2*l2 + 1) * 64 + d;
    g_vh[idx] = (uint32_t)th[i0] | ((uint32_t)th[i1] << 16);
}

// ---------------------------------------------------------------------------
// bf16x3 GEMM (R4-validated): block 128x128, K-tile 32, 256 threads (8 warps
// 64x32). EPI=0: QKV epilogue -> f16 Q(hi/lo) / K(single) / Vt(single).
// EPI=1: plain f32 write + bias.
// ---------------------------------------------------------------------------
#define OAH 0
#define OAL 2560
#define OBH 5120
#define OBL 7296
#define STG 9472
#define GEMM_SMEM (2*STG*4)

template<int EPI>
__global__ void __launch_bounds__(256, 1)
gemm_bf16x3(const uint32_t* __restrict__ Ah, const uint32_t* __restrict__ Al,
            const uint32_t* __restrict__ Bh, const uint32_t* __restrict__ Bl,
            const float* __restrict__ bias, float* __restrict__ outp, int N)
{
    extern __shared__ uint32_t sm[];
    const int tid  = threadIdx.x;
    const int lane = tid & 31;
    const int wid  = tid >> 5;
    const int wm   = wid >> 2;
    const int wn   = wid & 3;
    const int m0   = blockIdx.y * 128;
    const int n0   = blockIdx.x * 128;
    const int KP2  = 512;

    const uint32_t sbase = (uint32_t)__cvta_generic_to_shared(sm);

    float C[4][4][4];
#pragma unroll
    for (int mt = 0; mt < 4; mt++)
#pragma unroll
        for (int nt = 0; nt < 4; nt++)
#pragma unroll
            for (int e = 0; e < 4; e++) C[mt][nt][e] = 0.f;

    auto load_stage = [&](int s, int kp0) {
        uint32_t sa = sbase + (uint32_t)(s * STG) * 4;
#pragma unroll
        for (int j = tid; j < 512; j += 256) {
            int row = j >> 2, c4 = (j & 3) << 2;
            cp16(sa + (OAH + row*20 + c4)*4, Ah + (size_t)(m0+row)*KP2 + kp0 + c4);
            cp16(sa + (OAL + row*20 + c4)*4, Al + (size_t)(m0+row)*KP2 + kp0 + c4);
        }
#pragma unroll
        for (int j = tid; j < 512; j += 256) {
            int row = j >> 5, c4 = (j & 31) << 2;
            cp16(sa + (OBH + row*136 + c4)*4, Bh + (size_t)(kp0+row)*N + n0 + c4);
            cp16(sa + (OBL + row*136 + c4)*4, Bl + (size_t)(kp0+row)*N + n0 + c4);
        }
    };

    load_stage(0, 0);
    cp_commit();

    const int T = 32;
    for (int t = 0; t < T; t++) {
        if (t + 1 < T) { load_stage((t+1)&1, (t+1)*16); cp_commit(); }
        if (t + 1 < T) asm volatile("cp.async.wait_group 1;\n" ::: "memory");
        else           asm volatile("cp.async.wait_group 0;\n" ::: "memory");
        __syncthreads();

        const uint32_t* S = sm + (t & 1) * STG;
#pragma unroll
        for (int ss = 0; ss < 2; ss++) {
            const int c2 = ss*8 + (lane & 3);
            uint32_t ah[4][4], al[4][4];
#pragma unroll
            for (int mt = 0; mt < 4; mt++) {
                const int r0 = wm*64 + mt*16 + (lane >> 2);
                ah[mt][0] = S[OAH + r0*20 + c2];
                ah[mt][1] = S[OAH + (r0+8)*20 + c2];
                ah[mt][2] = S[OAH + r0*20 + c2 + 4];
                ah[mt][3] = S[OAH + (r0+8)*20 + c2 + 4];
                al[mt][0] = S[OAL + r0*20 + c2];
                al[mt][1] = S[OAL + (r0+8)*20 + c2];
                al[mt][2] = S[OAL + r0*20 + c2 + 4];
                al[mt][3] = S[OAL + (r0+8)*20 + c2 + 4];
            }
            uint32_t bh[4][2], bl[4][2];
            const int k2 = ss*8 + (lane & 3);
#pragma unroll
            for (int nt = 0; nt < 4; nt++) {
                const int col = wn*32 + nt*8 + (lane >> 2);
                bh[nt][0] = S[OBH + k2*136 + col];
                bh[nt][1] = S[OBH + (k2+4)*136 + col];
                bl[nt][0] = S[OBL + k2*136 + col];
                bl[nt][1] = S[OBL + (k2+4)*136 + col];
            }
#pragma unroll
            for (int mt = 0; mt < 4; mt++)
#pragma unroll
                for (int nt = 0; nt < 4; nt++) {
                    mma16816(C[mt][nt], ah[mt], bh[nt]);
                    mma16816(C[mt][nt], ah[mt], bl[nt]);
                    mma16816(C[mt][nt], al[mt], bh[nt]);
                }
        }
        __syncthreads();
    }

    // Epilogue
#pragma unroll
    for (int mt = 0; mt < 4; mt++) {
#pragma unroll
        for (int nt = 0; nt < 4; nt++) {
            const int r = m0 + wm*64 + mt*16 + (lane >> 2);
            const int c = n0 + wn*32 + nt*8 + (lane & 3)*2;
            const float b0 = bias[c], b1 = bias[c+1];
            const float v00 = C[mt][nt][0]+b0, v01 = C[mt][nt][1]+b1;
            const float v10 = C[mt][nt][2]+b0, v11 = C[mt][nt][3]+b1;
            if (EPI == 0) {
                const int part = c >> 10;
                const int d   = c & 1023;
                const int h   = d >> 6;
                const int dk2 = (d & 63) >> 1;
                const int bI  = r >> 11;
                const int l   = r & 2047;
                const int bh  = bI*16 + h;
                if (part == 0) {
                    uint32_t lo0, lo1;
                    uint32_t hi0 = pack_hl_f16(v00, v01, lo0);
                    uint32_t hi1 = pack_hl_f16(v10, v11, lo1);
                    size_t i0 = ((size_t)bh*2048 + l)*32 + dk2;
                    g_qh[i0] = hi0;        g_ql[i0] = lo0;
                    g_qh[i0 + 8*32] = hi1; g_ql[i0 + 8*32] = lo1;
                } else if (part == 1) {
                    size_t i0 = ((size_t)bh*32 + dk2)*2048 + l;
                    g_kh[i0]     = pack_h2(v00, v01);
                    g_kh[i0 + 8] = pack_h2(v10, v11);
                } else {
                    size_t i0 = ((size_t)bh*2048 + l)*32 + dk2;
                    g_vth[i0]        = pack_h2(v00, v01);
                    g_vth[i0 + 8*32] = pack_h2(v10, v11);
                }
            } else {
                *(float2*)&outp[(size_t)r*N + c]     = make_float2(v00, v01);
                *(float2*)&outp[(size_t)(r+8)*N + c] = make_float2(v10, v11);
            }
        }
    }
}

// ---------------------------------------------------------------------------
// f16 flash attention: 128 queries/CTA, 8 warps.
// S = qh*kh + ql*kh (2 passes); PV = ph*vh + pl*vh (2 passes).
// ---------------------------------------------------------------------------
#define AKH 0
#define AVH 2304
#define ASTG 4608
#define ATTN_SMEM (2*ASTG*4)   // 36864 bytes

__device__ __forceinline__ void softmax_row(float (&sC)[8][4], float (&oC)[8][4],
                                            int e0, uint32_t w0, uint32_t w1,
                                            int c, float& mi, float& li)
{
    float rm = -1e30f;
    uint32_t rbits = 0;
#pragma unroll
    for (int j = 0; j < 8; j++) {
        const uint32_t w = (j < 4) ? w0 : w1;
#pragma unroll
        for (int e = 0; e < 2; e++) {
            const int col = 8*j + 2*c + e;
            const uint32_t bit = (w >> (col & 31)) & 1u;
            const float sv = bit ? sC[j][e0+e]*SCALE_ : 0.f;
            sC[j][e0+e] = sv;
            rbits |= bit << (2*j + e);
            rm = fmaxf(rm, sv);
        }
    }
    rm = fmaxf(rm, __shfl_xor_sync(0xffffffffu, rm, 1));
    rm = fmaxf(rm, __shfl_xor_sync(0xffffffffu, rm, 2));
    const float mn  = fmaxf(mi, rm);
    const float fac = __expf(mi - mn);
    float rs = 0.f;
#pragma unroll
    for (int j = 0; j < 8; j++)
#pragma unroll
        for (int e = 0; e < 2; e++) {
            const float pd = __expf(sC[j][e0+e] - mn);
            rs += pd;
            sC[j][e0+e] = ((rbits >> (2*j + e)) & 1u) ? pd : 0.f;
        }
    rs += __shfl_xor_sync(0xffffffffu, rs, 1);
    rs += __shfl_xor_sync(0xffffffffu, rs, 2);
    li = li*fac + rs;
    mi = mn;
#pragma unroll
    for (int j = 0; j < 8; j++) { oC[j][e0] *= fac; oC[j][e0+1] *= fac; }
}

__global__ void __launch_bounds__(256, 1)
attn_mma_kernel()
{
    extern __shared__ uint32_t sm[];
    const int tid  = threadIdx.x;
    const int lane = tid & 31;
    const int wid  = tid >> 5;
    const int c    = lane & 3;
    const int rq   = lane >> 2;
    const int bh   = blockIdx.y;
    const int b    = bh >> 4;
    const int h    = bh & 15;
    const int q0   = blockIdx.x * 128;
    const int r0   = q0 + wid*16 + rq;

    const uint32_t sbase = (uint32_t)__cvta_generic_to_shared(sm);

    uint32_t qh[4][4], ql[4][4];
    {
        const uint32_t* Qh = g_qh + (size_t)bh*2048*32;
        const uint32_t* Ql = g_ql + (size_t)bh*2048*32;
#pragma unroll
        for (int t = 0; t < 4; t++) {
            qh[t][0] = Qh[(size_t)r0*32     + 8*t + c];
            qh[t][1] = Qh[(size_t)(r0+8)*32 + 8*t + c];
            qh[t][2] = Qh[(size_t)r0*32     + 8*t + c + 4];
            qh[t][3] = Qh[(size_t)(r0+8)*32 + 8*t + c + 4];
            ql[t][0] = Ql[(size_t)r0*32     + 8*t + c];
            ql[t][1] = Ql[(size_t)(r0+8)*32 + 8*t + c];
            ql[t][2] = Ql[(size_t)r0*32     + 8*t + c + 4];
            ql[t][3] = Ql[(size_t)(r0+8)*32 + 8*t + c + 4];
        }
    }

    float oC[8][4];
#pragma unroll
    for (int j = 0; j < 8; j++)
#pragma unroll
        for (int e = 0; e < 4; e++) oC[j][e] = 0.f;
    float mi[2] = {-1e30f, -1e30f};
    float li[2] = {0.f, 0.f};

    auto load_stage = [&](int s, int k0) {
        const uint32_t sa = sbase + (uint32_t)(s * ASTG) * 4;
#pragma unroll
        for (int it = 0; it < 2; it++) {
            const int idx = it*256 + tid;
            const int row = idx >> 4;
            const int c4  = (idx & 15) * 4;
            cp16(sa + (AKH + row*72 + c4)*4, g_kh + ((size_t)bh*32 + row)*2048 + k0 + c4);
            cp16(sa + (AVH + row*72 + c4)*4, g_vh + ((size_t)bh*1024 + (k0>>1) + row)*64 + c4);
        }
    };

    load_stage(0, 0);
    cp_commit();

    const uint32_t* MB = g_mb + (size_t)b*2048*64;

    for (int t32 = 0; t32 < 32; t32++) {
        const int k0 = t32 * 64;
        if (t32 + 1 < 32) { load_stage((t32+1)&1, k0 + 64); cp_commit(); }
        if (t32 + 1 < 32) asm volatile("cp.async.wait_group 1;\n" ::: "memory");
        else              asm volatile("cp.async.wait_group 0;\n" ::: "memory");
        __syncthreads();

        const uint32_t* S = sm + (t32 & 1) * ASTG;

        float sC[8][4];
#pragma unroll
        for (int j = 0; j < 8; j++)
#pragma unroll
            for (int e = 0; e < 4; e++) sC[j][e] = 0.f;

        // ---- S = Q @ K^T : qh*kh + ql*kh ----
#pragma unroll
        for (int t = 0; t < 4; t++) {
#pragma unroll
            for (int jj = 0; jj < 4; jj++) {
                const int j0 = 2*jj, j1 = 2*jj + 1;
                uint32_t b0[2], b1[2];
                b0[0] = S[AKH + (8*t + c)*72     + 8*j0 + rq];
                b0[1] = S[AKH + (8*t + c + 4)*72 + 8*j0 + rq];
                b1[0] = S[AKH + (8*t + c)*72     + 8*j1 + rq];
                b1[1] = S[AKH + (8*t + c + 4)*72 + 8*j1 + rq];
                mma_f16(sC[j0], qh[t], b0);
                mma_f16(sC[j1], qh[t], b1);
                mma_f16(sC[j0], ql[t], b0);
                mma_f16(sC[j1], ql[t], b1);
            }
        }

        const int wbase = k0 >> 5;
        const uint32_t w00 = MB[(size_t)r0*64 + wbase],     w01 = MB[(size_t)r0*64 + wbase + 1];
        const uint32_t w10 = MB[(size_t)(r0+8)*64 + wbase], w11 = MB[(size_t)(r0+8)*64 + wbase + 1];
        softmax_row(sC, oC, 0, w00, w01, c, mi[0], li[0]);
        softmax_row(sC, oC, 2, w10, w11, c, mi[1], li[1]);

        // ---- O += P @ V : ph*vh + pl*vh ----
#pragma unroll
        for (int tp = 0; tp < 4; tp++) {
            uint32_t pah[4], pal[4];
            pah[0] = pack_hl_f16(sC[2*tp][0],   sC[2*tp][1],   pal[0]);
            pah[1] = pack_hl_f16(sC[2*tp][2],   sC[2*tp][3],   pal[1]);
            pah[2] = pack_hl_f16(sC[2*tp+1][0], sC[2*tp+1][1], pal[2]);
            pah[3] = pack_hl_f16(sC[2*tp+1][2], sC[2*tp+1][3], pal[3]);
#pragma unroll
            for (int jj = 0; jj < 4; jj++) {
                const int j0 = 2*jj, j1 = 2*jj + 1;
                uint32_t b0[2], b1[2];
                b0[0] = S[AVH + (8*tp + c)*72     + 8*j0 + rq];
                b0[1] = S[AVH + (8*tp + c + 4)*72 + 8*j0 + rq];
                b1[0] = S[AVH + (8*tp + c)*72     + 8*j1 + rq];
                b1[1] = S[AVH + (8*tp + c + 4)*72 + 8*j1 + rq];
                mma_f16(oC[j0], pah, b0);
                mma_f16(oC[j1], pah, b1);
                mma_f16(oC[j0], pal, b0);
                mma_f16(oC[j1], pal, b1);
            }
        }
        __syncthreads();
    }

    // normalize + emit out-proj A operand (bf16 hi/lo, for bf16x3 out-proj)
    const float inv0 = 1.0f / li[0];
    const float inv1 = 1.0f / li[1];
    const size_t mrow = (size_t)b*2048 + r0;
#pragma unroll
    for (int j = 0; j < 8; j++) {
        const int k2 = h*32 + 4*j + c;
        uint32_t lo0, lo1;
        uint32_t hi0 = pack_hl(oC[j][0]*inv0, oC[j][1]*inv0, lo0);
        uint32_t hi1 = pack_hl(oC[j][2]*inv1, oC[j][3]*inv1, lo1);
        g_oh[mrow*512 + k2]     = hi0;  g_ol[mrow*512 + k2]     = lo0;
        g_oh[(mrow+8)*512 + k2] = hi1;  g_ol[(mrow+8)*512 + k2] = lo1;
    }
}

// ---------------------------------------------------------------------------

extern "C" void kernel_launch(void* const* d_in, const int* in_sizes, int n_in,
                              void* d_out, int out_size)
{
    const float* x     = (const float*)d_in[0];
    const int*   mask  = (const int*)  d_in[1];
    const float* W_qkv = (const float*)d_in[2];
    const float* b_qkv = (const float*)d_in[3];
    const float* W_out = (const float*)d_in[4];
    const float* b_out = (const float*)d_in[5];
    float* out = (float*)d_out;

    cudaFuncSetAttribute(gemm_bf16x3<0>, cudaFuncAttributeMaxDynamicSharedMemorySize, GEMM_SMEM);
    cudaFuncSetAttribute(gemm_bf16x3<1>, cudaFuncAttributeMaxDynamicSharedMemorySize, GEMM_SMEM);
    cudaFuncSetAttribute(attn_mma_kernel, cudaFuncAttributeMaxDynamicSharedMemorySize, ATTN_SMEM);

    uint32_t *xh, *xl, *wqh, *wql, *oh, *ol, *woh, *wol;
    cudaGetSymbolAddress((void**)&xh,  g_xh);
    cudaGetSymbolAddress((void**)&xl,  g_xl);
    cudaGetSymbolAddress((void**)&wqh, g_wqh);
    cudaGetSymbolAddress((void**)&wql, g_wql);
    cudaGetSymbolAddress((void**)&oh,  g_oh);
    cudaGetSymbolAddress((void**)&ol,  g_ol);
    cudaGetSymbolAddress((void**)&woh, g_woh);
    cudaGetSymbolAddress((void**)&wol, g_wol);

    // Splits
    split_A<<<(4096*512)/256, 256>>>(x, xh, xl, 4096*512);
    split_B<<<dim3(3072/256, 512), 256>>>(W_qkv, wqh, wql, 3072);
    maskpack<<<(2*2048*64)/256, 256>>>(mask);

    // QKV projection -> f16 Q(hi/lo) / K / Vt
    gemm_bf16x3<0><<<dim3(24, 32), 256, GEMM_SMEM>>>(xh, xl, wqh, wql, b_qkv, nullptr, 3072);

    // V repack (pairs along keys)
    vrepack<<<(32*1024*64)/256, 256>>>();

    // Attention (f16, 2+2 passes) -> g_oh/g_ol
    attn_mma_kernel<<<dim3(16, 32), 256, ATTN_SMEM>>>();

    // Output projection (bf16x3)
    split_B<<<dim3(1024/256, 512), 256>>>(W_out, woh, wol, 1024);
    gemm_bf16x3<1><<<dim3(8, 32), 256, GEMM_SMEM>>>(oh, ol, woh, wol, b_out, out, 1024);
}

// round 11
// speedup vs baseline: 1.4679x; 1.1410x over previous
#include <cuda_runtime.h>
#include <cuda_bf16.h>
#include <cuda_fp16.h>
#include <cstdint>

#define SCALE_ 0.125f   // 1/sqrt(64)

// f16 GEMM operands (u32 = packed f16x2 along k-pairs)
__device__ uint32_t g_xh [4096*512], g_xl [4096*512];   // X hi/lo [M][K/2]
__device__ uint32_t g_wqh[512*3072];                    // Wqkv single [K/2][N]
__device__ uint32_t g_oh [4096*512], g_ol [4096*512];   // attnO hi/lo [M][K/2]
__device__ uint32_t g_woh[512*1024];                    // Wout single [K/2][N]

// attention operands (f16)
__device__ uint32_t g_qh [32*2048*32], g_ql [32*2048*32]; // Q hi/lo [bh][l][dk2]
__device__ uint32_t g_kh [32*32*2048];                    // K single [bh][dk2][l]
__device__ uint32_t g_vth[32*2048*32];                    // Vt single [bh][l][dk2]
__device__ uint32_t g_vh [32*1024*64];                    // V single [bh][l2][dk]
__device__ uint32_t g_mb [2*2048*64];                     // mask bits

// ---------------------------------------------------------------------------
// Helpers
// ---------------------------------------------------------------------------
__device__ __forceinline__ uint32_t pack_h2(float a, float b) {
    __half2 h = __floats2half2_rn(a, b);
    return *reinterpret_cast<uint32_t*>(&h);
}
__device__ __forceinline__ uint32_t pack_hl_f16(float a, float b, uint32_t& lo) {
    __half2 t = __floats2half2_rn(a, b);
    float ra = a - __half2float(t.x);
    float rb = b - __half2float(t.y);
    __half2 u = __floats2half2_rn(ra, rb);
    lo = *reinterpret_cast<uint32_t*>(&u);
    return *reinterpret_cast<uint32_t*>(&t);
}
__device__ __forceinline__ void cp16(uint32_t saddr, const void* gptr) {
    asm volatile("cp.async.cg.shared.global [%0], [%1], 16;\n" :: "r"(saddr), "l"(gptr));
}
__device__ __forceinline__ void cp_commit() {
    asm volatile("cp.async.commit_group;\n" ::: "memory");
}
__device__ __forceinline__ void mma_f16(float* c, const uint32_t* a, const uint32_t* b) {
    asm volatile(
        "mma.sync.aligned.m16n8k16.row.col.f32.f16.f16.f32 "
        "{%0,%1,%2,%3}, {%4,%5,%6,%7}, {%8,%9}, {%0,%1,%2,%3};\n"
        : "+f"(c[0]), "+f"(c[1]), "+f"(c[2]), "+f"(c[3])
        : "r"(a[0]), "r"(a[1]), "r"(a[2]), "r"(a[3]), "r"(b[0]), "r"(b[1]));
}

// ---------------------------------------------------------------------------
// Operand prep kernels
// ---------------------------------------------------------------------------
// A [M][1024] f32 -> f16 hi/lo packed pairs [M][512]
__global__ void split_A_f16(const float* __restrict__ in,
                            uint32_t* __restrict__ h, uint32_t* __restrict__ l, int n)
{
    int i = blockIdx.x * blockDim.x + threadIdx.x;
    if (i >= n) return;
    float2 a = ((const float2*)in)[i];
    uint32_t lo;
    uint32_t hi = pack_hl_f16(a.x, a.y, lo);
    h[i] = hi; l[i] = lo;
}

// W [1024][N] f32 -> single f16 packed pairs [512][N]
__global__ void split_B_f16(const float* __restrict__ in,
                            uint32_t* __restrict__ h, int N)
{
    int n  = blockIdx.x * blockDim.x + threadIdx.x;
    int k2 = blockIdx.y;
    float a0 = in[(size_t)(2*k2)   * N + n];
    float a1 = in[(size_t)(2*k2+1) * N + n];
    h[(size_t)k2 * N + n] = pack_h2(a0, a1);
}

__global__ void maskpack(const int* __restrict__ mask)
{
    int idx = blockIdx.x * 256 + threadIdx.x;
    int w   = idx & 63;
    int row = idx >> 6;
    const int4* p = (const int4*)(mask + (size_t)row * 2048 + w * 32);
    uint32_t bits = 0;
#pragma unroll
    for (int i = 0; i < 8; i++) {
        int4 v = p[i];
        bits |= (uint32_t)(v.x != 0) << (4*i)
             |  (uint32_t)(v.y != 0) << (4*i+1)
             |  (uint32_t)(v.z != 0) << (4*i+2)
             |  (uint32_t)(v.w != 0) << (4*i+3);
    }
    g_mb[idx] = bits;
}

// V repack: [bh][l][dk2] (pairs along dk, f16) -> [bh][l2][dk] (pairs along l)
__global__ void vrepack()
{
    int idx = blockIdx.x * 256 + threadIdx.x;
    int d  = idx & 63;
    int l2 = (idx >> 6) & 1023;
    int bh = idx >> 16;
    const uint16_t* th = (const uint16_t*)g_vth;
    size_t i0 = ((size_t)bh*2048 + 2*l2    ) * 64 + d;
    size_t i1 = ((size_t)bh*2048 + 2*l2 + 1) * 64 + d;
    g_vh[idx] = (uint32_t)th[i0] | ((uint32_t)th[i1] << 16);
}

// ---------------------------------------------------------------------------
// f16x2 GEMM: C = A*B, A split f16 hi/lo, B single f16 (2 MMAs per k16).
// Block 128x128, K-tile 32, 256 threads (8 warps, warp 64x32).
// EPI=0: QKV epilogue -> f16 Q(hi/lo) / K(single) / Vt(single).
// EPI=1: plain f32 write + bias.
// ---------------------------------------------------------------------------
#define OAH 0
#define OAL 2560
#define OB  5120
#define STG 7296
#define GEMM_SMEM (2*STG*4)   // 58368 B

template<int EPI>
__global__ void __launch_bounds__(256, 1)
gemm_f16x2(const uint32_t* __restrict__ Ah, const uint32_t* __restrict__ Al,
           const uint32_t* __restrict__ Bh,
           const float* __restrict__ bias, float* __restrict__ outp, int N)
{
    extern __shared__ uint32_t sm[];
    const int tid  = threadIdx.x;
    const int lane = tid & 31;
    const int wid  = tid >> 5;
    const int wm   = wid >> 2;      // 0..1 -> 64-row band
    const int wn   = wid & 3;       // 0..3 -> 32-col band
    const int m0   = blockIdx.y * 128;
    const int n0   = blockIdx.x * 128;
    const int KP2  = 512;

    const uint32_t sbase = (uint32_t)__cvta_generic_to_shared(sm);

    float C[4][4][4];
#pragma unroll
    for (int mt = 0; mt < 4; mt++)
#pragma unroll
        for (int nt = 0; nt < 4; nt++)
#pragma unroll
            for (int e = 0; e < 4; e++) C[mt][nt][e] = 0.f;

    auto load_stage = [&](int s, int kp0) {
        uint32_t sa = sbase + (uint32_t)(s * STG) * 4;
#pragma unroll
        for (int j = tid; j < 512; j += 256) {
            int row = j >> 2, c4 = (j & 3) << 2;
            cp16(sa + (OAH + row*20 + c4)*4, Ah + (size_t)(m0+row)*KP2 + kp0 + c4);
            cp16(sa + (OAL + row*20 + c4)*4, Al + (size_t)(m0+row)*KP2 + kp0 + c4);
        }
#pragma unroll
        for (int j = tid; j < 512; j += 256) {
            int row = j >> 5, c4 = (j & 31) << 2;
            cp16(sa + (OB + row*136 + c4)*4, Bh + (size_t)(kp0+row)*N + n0 + c4);
        }
    };

    load_stage(0, 0);
    cp_commit();

    const int T = 32;
    for (int t = 0; t < T; t++) {
        if (t + 1 < T) { load_stage((t+1)&1, (t+1)*16); cp_commit(); }
        if (t + 1 < T) asm volatile("cp.async.wait_group 1;\n" ::: "memory");
        else           asm volatile("cp.async.wait_group 0;\n" ::: "memory");
        __syncthreads();

        const uint32_t* S = sm + (t & 1) * STG;
#pragma unroll
        for (int ss = 0; ss < 2; ss++) {
            const int c2 = ss*8 + (lane & 3);
            uint32_t ah[4][4], al[4][4];
#pragma unroll
            for (int mt = 0; mt < 4; mt++) {
                const int r0 = wm*64 + mt*16 + (lane >> 2);
                ah[mt][0] = S[OAH + r0*20 + c2];
                ah[mt][1] = S[OAH + (r0+8)*20 + c2];
                ah[mt][2] = S[OAH + r0*20 + c2 + 4];
                ah[mt][3] = S[OAH + (r0+8)*20 + c2 + 4];
                al[mt][0] = S[OAL + r0*20 + c2];
                al[mt][1] = S[OAL + (r0+8)*20 + c2];
                al[mt][2] = S[OAL + r0*20 + c2 + 4];
                al[mt][3] = S[OAL + (r0+8)*20 + c2 + 4];
            }
            uint32_t bh[4][2];
            const int k2 = c2;
#pragma unroll
            for (int nt = 0; nt < 4; nt++) {
                const int col = wn*32 + nt*8 + (lane >> 2);
                bh[nt][0] = S[OB + k2*136 + col];
                bh[nt][1] = S[OB + (k2+4)*136 + col];
            }
#pragma unroll
            for (int mt = 0; mt < 4; mt++)
#pragma unroll
                for (int nt = 0; nt < 4; nt++) {
                    mma_f16(C[mt][nt], ah[mt], bh[nt]);
                    mma_f16(C[mt][nt], al[mt], bh[nt]);
                }
        }
        __syncthreads();
    }

    // Epilogue
#pragma unroll
    for (int mt = 0; mt < 4; mt++) {
#pragma unroll
        for (int nt = 0; nt < 4; nt++) {
            const int r = m0 + wm*64 + mt*16 + (lane >> 2);
            const int c = n0 + wn*32 + nt*8 + (lane & 3)*2;
            const float b0 = bias[c], b1 = bias[c+1];
            const float v00 = C[mt][nt][0]+b0, v01 = C[mt][nt][1]+b1;
            const float v10 = C[mt][nt][2]+b0, v11 = C[mt][nt][3]+b1;
            if (EPI == 0) {
                const int part = c >> 10;
                const int d   = c & 1023;
                const int h   = d >> 6;
                const int dk2 = (d & 63) >> 1;
                const int bI  = r >> 11;
                const int l   = r & 2047;
                const int bh  = bI*16 + h;
                if (part == 0) {
                    uint32_t lo0, lo1;
                    uint32_t hi0 = pack_hl_f16(v00, v01, lo0);
                    uint32_t hi1 = pack_hl_f16(v10, v11, lo1);
                    size_t i0 = ((size_t)bh*2048 + l)*32 + dk2;
                    g_qh[i0] = hi0;        g_ql[i0] = lo0;
                    g_qh[i0 + 8*32] = hi1; g_ql[i0 + 8*32] = lo1;
                } else if (part == 1) {
                    size_t i0 = ((size_t)bh*32 + dk2)*2048 + l;
                    g_kh[i0]     = pack_h2(v00, v01);
                    g_kh[i0 + 8] = pack_h2(v10, v11);
                } else {
                    size_t i0 = ((size_t)bh*2048 + l)*32 + dk2;
                    g_vth[i0]        = pack_h2(v00, v01);
                    g_vth[i0 + 8*32] = pack_h2(v10, v11);
                }
            } else {
                *(float2*)&outp[(size_t)r*N + c]     = make_float2(v00, v01);
                *(float2*)&outp[(size_t)(r+8)*N + c] = make_float2(v10, v11);
            }
        }
    }
}

// ---------------------------------------------------------------------------
// f16 flash attention (R10-validated): 128 queries/CTA, 8 warps.
// S = qh*kh + ql*kh (2 passes); PV = ph*vh + pl*vh (2 passes).
// ---------------------------------------------------------------------------
#define AKH 0
#define AVH 2304
#define ASTG 4608
#define ATTN_SMEM (2*ASTG*4)   // 36864 bytes

__device__ __forceinline__ void softmax_row(float (&sC)[8][4], float (&oC)[8][4],
                                            int e0, uint32_t w0, uint32_t w1,
                                            int c, float& mi, float& li)
{
    float rm = -1e30f;
    uint32_t rbits = 0;
#pragma unroll
    for (int j = 0; j < 8; j++) {
        const uint32_t w = (j < 4) ? w0 : w1;
#pragma unroll
        for (int e = 0; e < 2; e++) {
            const int col = 8*j + 2*c + e;
            const uint32_t bit = (w >> (col & 31)) & 1u;
            const float sv = bit ? sC[j][e0+e]*SCALE_ : 0.f;
            sC[j][e0+e] = sv;
            rbits |= bit << (2*j + e);
            rm = fmaxf(rm, sv);
        }
    }
    rm = fmaxf(rm, __shfl_xor_sync(0xffffffffu, rm, 1));
    rm = fmaxf(rm, __shfl_xor_sync(0xffffffffu, rm, 2));
    const float mn  = fmaxf(mi, rm);
    const float fac = __expf(mi - mn);
    float rs = 0.f;
#pragma unroll
    for (int j = 0; j < 8; j++)
#pragma unroll
        for (int e = 0; e < 2; e++) {
            const float pd = __expf(sC[j][e0+e] - mn);
            rs += pd;
            sC[j][e0+e] = ((rbits >> (2*j + e)) & 1u) ? pd : 0.f;
        }
    rs += __shfl_xor_sync(0xffffffffu, rs, 1);
    rs += __shfl_xor_sync(0xffffffffu, rs, 2);
    li = li*fac + rs;
    mi = mn;
#pragma unroll
    for (int j = 0; j < 8; j++) { oC[j][e0] *= fac; oC[j][e0+1] *= fac; }
}

__global__ void __launch_bounds__(256, 1)
attn_mma_kernel()
{
    extern __shared__ uint32_t sm[];
    const int tid  = threadIdx.x;
    const int lane = tid & 31;
    const int wid  = tid >> 5;
    const int c    = lane & 3;
    const int rq   = lane >> 2;
    const int bh   = blockIdx.y;
    const int b    = bh >> 4;
    const int h    = bh & 15;
    const int q0   = blockIdx.x * 128;
    const int r0   = q0 + wid*16 + rq;

    const uint32_t sbase = (uint32_t)__cvta_generic_to_shared(sm);

    uint32_t qh[4][4], ql[4][4];
    {
        const uint32_t* Qh = g_qh + (size_t)bh*2048*32;
        const uint32_t* Ql = g_ql + (size_t)bh*2048*32;
#pragma unroll
        for (int t = 0; t < 4; t++) {
            qh[t][0] = Qh[(size_t)r0*32     + 8*t + c];
            qh[t][1] = Qh[(size_t)(r0+8)*32 + 8*t + c];
            qh[t][2] = Qh[(size_t)r0*32     + 8*t + c + 4];
            qh[t][3] = Qh[(size_t)(r0+8)*32 + 8*t + c + 4];
            ql[t][0] = Ql[(size_t)r0*32     + 8*t + c];
            ql[t][1] = Ql[(size_t)(r0+8)*32 + 8*t + c];
            ql[t][2] = Ql[(size_t)r0*32     + 8*t + c + 4];
            ql[t][3] = Ql[(size_t)(r0+8)*32 + 8*t + c + 4];
        }
    }

    float oC[8][4];
#pragma unroll
    for (int j = 0; j < 8; j++)
#pragma unroll
        for (int e = 0; e < 4; e++) oC[j][e] = 0.f;
    float mi[2] = {-1e30f, -1e30f};
    float li[2] = {0.f, 0.f};

    auto load_stage = [&](int s, int k0) {
        const uint32_t sa = sbase + (uint32_t)(s * ASTG) * 4;
#pragma unroll
        for (int it = 0; it < 2; it++) {
            const int idx = it*256 + tid;
            const int row = idx >> 4;
            const int c4  = (idx & 15) * 4;
            cp16(sa + (AKH + row*72 + c4)*4, g_kh + ((size_t)bh*32 + row)*2048 + k0 + c4);
            cp16(sa + (AVH + row*72 + c4)*4, g_vh + ((size_t)bh*1024 + (k0>>1) + row)*64 + c4);
        }
    };

    load_stage(0, 0);
    cp_commit();

    const uint32_t* MB = g_mb + (size_t)b*2048*64;

    for (int t32 = 0; t32 < 32; t32++) {
        const int k0 = t32 * 64;
        if (t32 + 1 < 32) { load_stage((t32+1)&1, k0 + 64); cp_commit(); }
        if (t32 + 1 < 32) asm volatile("cp.async.wait_group 1;\n" ::: "memory");
        else              asm volatile("cp.async.wait_group 0;\n" ::: "memory");
        __syncthreads();

        const uint32_t* S = sm + (t32 & 1) * ASTG;

        float sC[8][4];
#pragma unroll
        for (int j = 0; j < 8; j++)
#pragma unroll
            for (int e = 0; e < 4; e++) sC[j][e] = 0.f;

        // ---- S = Q @ K^T : qh*kh + ql*kh ----
#pragma unroll
        for (int t = 0; t < 4; t++) {
#pragma unroll
            for (int jj = 0; jj < 4; jj++) {
                const int j0 = 2*jj, j1 = 2*jj + 1;
                uint32_t b0[2], b1[2];
                b0[0] = S[AKH + (8*t + c)*72     + 8*j0 + rq];
                b0[1] = S[AKH + (8*t + c + 4)*72 + 8*j0 + rq];
                b1[0] = S[AKH + (8*t + c)*72     + 8*j1 + rq];
                b1[1] = S[AKH + (8*t + c + 4)*72 + 8*j1 + rq];
                mma_f16(sC[j0], qh[t], b0);
                mma_f16(sC[j1], qh[t], b1);
                mma_f16(sC[j0], ql[t], b0);
                mma_f16(sC[j1], ql[t], b1);
            }
        }

        const int wbase = k0 >> 5;
        const uint32_t w00 = MB[(size_t)r0*64 + wbase],     w01 = MB[(size_t)r0*64 + wbase + 1];
        const uint32_t w10 = MB[(size_t)(r0+8)*64 + wbase], w11 = MB[(size_t)(r0+8)*64 + wbase + 1];
        softmax_row(sC, oC, 0, w00, w01, c, mi[0], li[0]);
        softmax_row(sC, oC, 2, w10, w11, c, mi[1], li[1]);

        // ---- O += P @ V : ph*vh + pl*vh ----
#pragma unroll
        for (int tp = 0; tp < 4; tp++) {
            uint32_t pah[4], pal[4];
            pah[0] = pack_hl_f16(sC[2*tp][0],   sC[2*tp][1],   pal[0]);
            pah[1] = pack_hl_f16(sC[2*tp][2],   sC[2*tp][3],   pal[1]);
            pah[2] = pack_hl_f16(sC[2*tp+1][0], sC[2*tp+1][1], pal[2]);
            pah[3] = pack_hl_f16(sC[2*tp+1][2], sC[2*tp+1][3], pal[3]);
#pragma unroll
            for (int jj = 0; jj < 4; jj++) {
                const int j0 = 2*jj, j1 = 2*jj + 1;
                uint32_t b0[2], b1[2];
                b0[0] = S[AVH + (8*tp + c)*72     + 8*j0 + rq];
                b0[1] = S[AVH + (8*tp + c + 4)*72 + 8*j0 + rq];
                b1[0] = S[AVH + (8*tp + c)*72     + 8*j1 + rq];
                b1[1] = S[AVH + (8*tp + c + 4)*72 + 8*j1 + rq];
                mma_f16(oC[j0], pah, b0);
                mma_f16(oC[j1], pah, b1);
                mma_f16(oC[j0], pal, b0);
                mma_f16(oC[j1], pal, b1);
            }
        }
        __syncthreads();
    }

    // normalize + emit out-proj A operand (f16 hi/lo)
    const float inv0 = 1.0f / li[0];
    const float inv1 = 1.0f / li[1];
    const size_t mrow = (size_t)b*2048 + r0;
#pragma unroll
    for (int j = 0; j < 8; j++) {
        const int k2 = h*32 + 4*j + c;
        uint32_t lo0, lo1;
        uint32_t hi0 = pack_hl_f16(oC[j][0]*inv0, oC[j][1]*inv0, lo0);
        uint32_t hi1 = pack_hl_f16(oC[j][2]*inv1, oC[j][3]*inv1, lo1);
        g_oh[mrow*512 + k2]     = hi0;  g_ol[mrow*512 + k2]     = lo0;
        g_oh[(mrow+8)*512 + k2] = hi1;  g_ol[(mrow+8)*512 + k2] = lo1;
    }
}

// ---------------------------------------------------------------------------

extern "C" void kernel_launch(void* const* d_in, const int* in_sizes, int n_in,
                              void* d_out, int out_size)
{
    const float* x     = (const float*)d_in[0];
    const int*   mask  = (const int*)  d_in[1];
    const float* W_qkv = (const float*)d_in[2];
    const float* b_qkv = (const float*)d_in[3];
    const float* W_out = (const float*)d_in[4];
    const float* b_out = (const float*)d_in[5];
    float* out = (float*)d_out;

    cudaFuncSetAttribute(gemm_f16x2<0>, cudaFuncAttributeMaxDynamicSharedMemorySize, GEMM_SMEM);
    cudaFuncSetAttribute(gemm_f16x2<1>, cudaFuncAttributeMaxDynamicSharedMemorySize, GEMM_SMEM);
    cudaFuncSetAttribute(attn_mma_kernel, cudaFuncAttributeMaxDynamicSharedMemorySize, ATTN_SMEM);

    uint32_t *xh, *xl, *wqh, *oh, *ol, *woh;
    cudaGetSymbolAddress((void**)&xh,  g_xh);
    cudaGetSymbolAddress((void**)&xl,  g_xl);
    cudaGetSymbolAddress((void**)&wqh, g_wqh);
    cudaGetSymbolAddress((void**)&oh,  g_oh);
    cudaGetSymbolAddress((void**)&ol,  g_ol);
    cudaGetSymbolAddress((void**)&woh, g_woh);

    // Operand prep
    split_A_f16<<<(4096*512)/256, 256>>>(x, xh, xl, 4096*512);
    split_B_f16<<<dim3(3072/256, 512), 256>>>(W_qkv, wqh, 3072);
    maskpack<<<(2*2048*64)/256, 256>>>(mask);

    // QKV projection (f16 2-pass) -> f16 Q(hi/lo) / K / Vt
    gemm_f16x2<0><<<dim3(24, 32), 256, GEMM_SMEM>>>(xh, xl, wqh, b_qkv, nullptr, 3072);

    // V repack (pairs along keys)
    vrepack<<<(32*1024*64)/256, 256>>>();

    // Attention (f16, 2+2 passes) -> g_oh/g_ol (f16 hi/lo)
    attn_mma_kernel<<<dim3(16, 32), 256, ATTN_SMEM>>>();

    // Output projection (f16 2-pass)
    split_B_f16<<<dim3(1024/256, 512), 256>>>(W_out, woh, 1024);
    gemm_f16x2<1><<<dim3(8, 32), 256, GEMM_SMEM>>>(oh, ol, woh, b_out, out, 1024);
}

// round 12
// speedup vs baseline: 2.0725x; 1.4119x over previous
#include <cuda_runtime.h>
#include <cuda_fp16.h>
#include <cstdint>

#define SCALE_ 0.125f   // 1/sqrt(64)

// f16 operands (u32 = packed f16x2 along k-pairs)
__device__ uint32_t g_xh [4096*512];    // X    [M][K/2]
__device__ uint32_t g_wqh[512*3072];    // Wqkv [K/2][N]
__device__ uint32_t g_oh [4096*512];    // attnO[M][K/2]
__device__ uint32_t g_woh[512*1024];    // Wout [K/2][N]

// attention operands (f16)
__device__ uint32_t g_qh [32*2048*32];  // Q [bh][l][dk2]
__device__ uint32_t g_kh [32*32*2048];  // K [bh][dk2][l]
__device__ uint32_t g_vh [32*1024*64];  // V [bh][l2][dk] (pairs along l)
__device__ uint32_t g_mb [2*2048*64];   // mask bits

// ---------------------------------------------------------------------------
// Helpers
// ---------------------------------------------------------------------------
__device__ __forceinline__ uint32_t pack_h2(float a, float b) {
    __half2 h = __floats2half2_rn(a, b);
    return *reinterpret_cast<uint32_t*>(&h);
}
__device__ __forceinline__ uint16_t f16bits(float a) {
    __half h = __float2half_rn(a);
    return *reinterpret_cast<uint16_t*>(&h);
}
__device__ __forceinline__ void cp16(uint32_t saddr, const void* gptr) {
    asm volatile("cp.async.cg.shared.global [%0], [%1], 16;\n" :: "r"(saddr), "l"(gptr));
}
__device__ __forceinline__ void cp_commit() {
    asm volatile("cp.async.commit_group;\n" ::: "memory");
}
__device__ __forceinline__ void mma_f16(float* c, const uint32_t* a, const uint32_t* b) {
    asm volatile(
        "mma.sync.aligned.m16n8k16.row.col.f32.f16.f16.f32 "
        "{%0,%1,%2,%3}, {%4,%5,%6,%7}, {%8,%9}, {%0,%1,%2,%3};\n"
        : "+f"(c[0]), "+f"(c[1]), "+f"(c[2]), "+f"(c[3])
        : "r"(a[0]), "r"(a[1]), "r"(a[2]), "r"(a[3]), "r"(b[0]), "r"(b[1]));
}

// ---------------------------------------------------------------------------
// Operand prep kernels
// ---------------------------------------------------------------------------
// A [M][1024] f32 -> f16 packed pairs [M][512]
__global__ void conv_A_f16(const float* __restrict__ in,
                           uint32_t* __restrict__ h, int n)
{
    int i = blockIdx.x * blockDim.x + threadIdx.x;
    if (i >= n) return;
    float2 a = ((const float2*)in)[i];
    h[i] = pack_h2(a.x, a.y);
}

// W [1024][N] f32 -> f16 packed pairs [512][N]
__global__ void split_B_f16(const float* __restrict__ in,
                            uint32_t* __restrict__ h, int N)
{
    int n  = blockIdx.x * blockDim.x + threadIdx.x;
    int k2 = blockIdx.y;
    float a0 = in[(size_t)(2*k2)   * N + n];
    float a1 = in[(size_t)(2*k2+1) * N + n];
    h[(size_t)k2 * N + n] = pack_h2(a0, a1);
}

__global__ void maskpack(const int* __restrict__ mask)
{
    int idx = blockIdx.x * 256 + threadIdx.x;
    int w   = idx & 63;
    int row = idx >> 6;
    const int4* p = (const int4*)(mask + (size_t)row * 2048 + w * 32);
    uint32_t bits = 0;
#pragma unroll
    for (int i = 0; i < 8; i++) {
        int4 v = p[i];
        bits |= (uint32_t)(v.x != 0) << (4*i)
             |  (uint32_t)(v.y != 0) << (4*i+1)
             |  (uint32_t)(v.z != 0) << (4*i+2)
             |  (uint32_t)(v.w != 0) << (4*i+3);
    }
    g_mb[idx] = bits;
}

// ---------------------------------------------------------------------------
// f16 single-pass GEMM: C = A*B, 1 MMA per k16.
// Block 128x128, K-tile 32, 256 threads (8 warps, warp 64x32).
// EPI=0: QKV epilogue -> f16 Q / K / V (V directly in [l2][dk] pair layout).
// EPI=1: plain f32 write + bias.
// ---------------------------------------------------------------------------
#define OA  0
#define OB  2560
#define STG 4736
#define GEMM_SMEM (2*STG*4)   // 37888 B

template<int EPI>
__global__ void __launch_bounds__(256, 1)
gemm_f16x1(const uint32_t* __restrict__ Ah,
           const uint32_t* __restrict__ Bh,
           const float* __restrict__ bias, float* __restrict__ outp, int N)
{
    extern __shared__ uint32_t sm[];
    const int tid  = threadIdx.x;
    const int lane = tid & 31;
    const int wid  = tid >> 5;
    const int wm   = wid >> 2;      // 0..1 -> 64-row band
    const int wn   = wid & 3;       // 0..3 -> 32-col band
    const int m0   = blockIdx.y * 128;
    const int n0   = blockIdx.x * 128;
    const int KP2  = 512;

    const uint32_t sbase = (uint32_t)__cvta_generic_to_shared(sm);

    float C[4][4][4];
#pragma unroll
    for (int mt = 0; mt < 4; mt++)
#pragma unroll
        for (int nt = 0; nt < 4; nt++)
#pragma unroll
            for (int e = 0; e < 4; e++) C[mt][nt][e] = 0.f;

    auto load_stage = [&](int s, int kp0) {
        uint32_t sa = sbase + (uint32_t)(s * STG) * 4;
#pragma unroll
        for (int j = tid; j < 512; j += 256) {
            int row = j >> 2, c4 = (j & 3) << 2;
            cp16(sa + (OA + row*20 + c4)*4, Ah + (size_t)(m0+row)*KP2 + kp0 + c4);
        }
#pragma unroll
        for (int j = tid; j < 512; j += 256) {
            int row = j >> 5, c4 = (j & 31) << 2;
            cp16(sa + (OB + row*136 + c4)*4, Bh + (size_t)(kp0+row)*N + n0 + c4);
        }
    };

    load_stage(0, 0);
    cp_commit();

    const int T = 32;
    for (int t = 0; t < T; t++) {
        if (t + 1 < T) { load_stage((t+1)&1, (t+1)*16); cp_commit(); }
        if (t + 1 < T) asm volatile("cp.async.wait_group 1;\n" ::: "memory");
        else           asm volatile("cp.async.wait_group 0;\n" ::: "memory");
        __syncthreads();

        const uint32_t* S = sm + (t & 1) * STG;
#pragma unroll
        for (int ss = 0; ss < 2; ss++) {
            const int c2 = ss*8 + (lane & 3);
            uint32_t ah[4][4];
#pragma unroll
            for (int mt = 0; mt < 4; mt++) {
                const int r0 = wm*64 + mt*16 + (lane >> 2);
                ah[mt][0] = S[OA + r0*20 + c2];
                ah[mt][1] = S[OA + (r0+8)*20 + c2];
                ah[mt][2] = S[OA + r0*20 + c2 + 4];
                ah[mt][3] = S[OA + (r0+8)*20 + c2 + 4];
            }
            uint32_t bh[4][2];
#pragma unroll
            for (int nt = 0; nt < 4; nt++) {
                const int col = wn*32 + nt*8 + (lane >> 2);
                bh[nt][0] = S[OB + c2*136 + col];
                bh[nt][1] = S[OB + (c2+4)*136 + col];
            }
#pragma unroll
            for (int mt = 0; mt < 4; mt++)
#pragma unroll
                for (int nt = 0; nt < 4; nt++)
                    mma_f16(C[mt][nt], ah[mt], bh[nt]);
        }
        __syncthreads();
    }

    // Epilogue
#pragma unroll
    for (int mt = 0; mt < 4; mt++) {
#pragma unroll
        for (int nt = 0; nt < 4; nt++) {
            const int r = m0 + wm*64 + mt*16 + (lane >> 2);
            const int c = n0 + wn*32 + nt*8 + (lane & 3)*2;
            const float b0 = bias[c], b1 = bias[c+1];
            const float v00 = C[mt][nt][0]+b0, v01 = C[mt][nt][1]+b1;
            const float v10 = C[mt][nt][2]+b0, v11 = C[mt][nt][3]+b1;
            if (EPI == 0) {
                const int part = c >> 10;
                const int d0  = c & 1023;
                const int h   = d0 >> 6;
                const int d   = d0 & 63;        // dk within head (even)
                const int dk2 = d >> 1;
                const int bI  = r >> 11;
                const int l   = r & 2047;
                const int bh  = bI*16 + h;
                if (part == 0) {
                    size_t i0 = ((size_t)bh*2048 + l)*32 + dk2;
                    g_qh[i0]        = pack_h2(v00, v01);
                    g_qh[i0 + 8*32] = pack_h2(v10, v11);
                } else if (part == 1) {
                    size_t i0 = ((size_t)bh*32 + dk2)*2048 + l;
                    g_kh[i0]     = pack_h2(v00, v01);
                    g_kh[i0 + 8] = pack_h2(v10, v11);
                } else {
                    // V directly in [bh][l2][dk] pair-along-l layout (u16 scatter)
                    uint16_t* V16 = (uint16_t*)g_vh;
                    const int p  = l & 1;
                    const int l2 = l >> 1;
                    size_t base0 = (((size_t)bh*1024 + l2    )*64 + d)*2 + p;
                    size_t base1 = (((size_t)bh*1024 + l2 + 4)*64 + d)*2 + p;
                    V16[base0]     = f16bits(v00);
                    V16[base0 + 2] = f16bits(v01);
                    V16[base1]     = f16bits(v10);
                    V16[base1 + 2] = f16bits(v11);
                }
            } else {
                *(float2*)&outp[(size_t)r*N + c]     = make_float2(v00, v01);
                *(float2*)&outp[(size_t)(r+8)*N + c] = make_float2(v10, v11);
            }
        }
    }
}

// ---------------------------------------------------------------------------
// f16 single-pass flash attention: 128 queries/CTA, 8 warps.
// S = q*k (1 pass); PV = p*v (1 pass). 64 MMAs per warp-tile-iter.
// ---------------------------------------------------------------------------
#define AKH 0
#define AVH 2304
#define ASTG 4608
#define ATTN_SMEM (2*ASTG*4)   // 36864 bytes

__device__ __forceinline__ void softmax_row(float (&sC)[8][4], float (&oC)[8][4],
                                            int e0, uint32_t w0, uint32_t w1,
                                            int c, float& mi, float& li)
{
    float rm = -1e30f;
    uint32_t rbits = 0;
#pragma unroll
    for (int j = 0; j < 8; j++) {
        const uint32_t w = (j < 4) ? w0 : w1;
#pragma unroll
        for (int e = 0; e < 2; e++) {
            const int col = 8*j + 2*c + e;
            const uint32_t bit = (w >> (col & 31)) & 1u;
            const float sv = bit ? sC[j][e0+e]*SCALE_ : 0.f;
            sC[j][e0+e] = sv;
            rbits |= bit << (2*j + e);
            rm = fmaxf(rm, sv);
        }
    }
    rm = fmaxf(rm, __shfl_xor_sync(0xffffffffu, rm, 1));
    rm = fmaxf(rm, __shfl_xor_sync(0xffffffffu, rm, 2));
    const float mn  = fmaxf(mi, rm);
    const float fac = __expf(mi - mn);
    float rs = 0.f;
#pragma unroll
    for (int j = 0; j < 8; j++)
#pragma unroll
        for (int e = 0; e < 2; e++) {
            const float pd = __expf(sC[j][e0+e] - mn);
            rs += pd;
            sC[j][e0+e] = ((rbits >> (2*j + e)) & 1u) ? pd : 0.f;
        }
    rs += __shfl_xor_sync(0xffffffffu, rs, 1);
    rs += __shfl_xor_sync(0xffffffffu, rs, 2);
    li = li*fac + rs;
    mi = mn;
#pragma unroll
    for (int j = 0; j < 8; j++) { oC[j][e0] *= fac; oC[j][e0+1] *= fac; }
}

__global__ void __launch_bounds__(256, 1)
attn_mma_kernel()
{
    extern __shared__ uint32_t sm[];
    const int tid  = threadIdx.x;
    const int lane = tid & 31;
    const int wid  = tid >> 5;
    const int c    = lane & 3;
    const int rq   = lane >> 2;
    const int bh   = blockIdx.y;
    const int b    = bh >> 4;
    const int h    = bh & 15;
    const int q0   = blockIdx.x * 128;
    const int r0   = q0 + wid*16 + rq;

    const uint32_t sbase = (uint32_t)__cvta_generic_to_shared(sm);

    uint32_t qh[4][4];
    {
        const uint32_t* Qh = g_qh + (size_t)bh*2048*32;
#pragma unroll
        for (int t = 0; t < 4; t++) {
            qh[t][0] = Qh[(size_t)r0*32     + 8*t + c];
            qh[t][1] = Qh[(size_t)(r0+8)*32 + 8*t + c];
            qh[t][2] = Qh[(size_t)r0*32     + 8*t + c + 4];
            qh[t][3] = Qh[(size_t)(r0+8)*32 + 8*t + c + 4];
        }
    }

    float oC[8][4];
#pragma unroll
    for (int j = 0; j < 8; j++)
#pragma unroll
        for (int e = 0; e < 4; e++) oC[j][e] = 0.f;
    float mi[2] = {-1e30f, -1e30f};
    float li[2] = {0.f, 0.f};

    auto load_stage = [&](int s, int k0) {
        const uint32_t sa = sbase + (uint32_t)(s * ASTG) * 4;
#pragma unroll
        for (int it = 0; it < 2; it++) {
            const int idx = it*256 + tid;
            const int row = idx >> 4;
            const int c4  = (idx & 15) * 4;
            cp16(sa + (AKH + row*72 + c4)*4, g_kh + ((size_t)bh*32 + row)*2048 + k0 + c4);
            cp16(sa + (AVH + row*72 + c4)*4, g_vh + ((size_t)bh*1024 + (k0>>1) + row)*64 + c4);
        }
    };

    load_stage(0, 0);
    cp_commit();

    const uint32_t* MB = g_mb + (size_t)b*2048*64;

    for (int t32 = 0; t32 < 32; t32++) {
        const int k0 = t32 * 64;
        if (t32 + 1 < 32) { load_stage((t32+1)&1, k0 + 64); cp_commit(); }
        if (t32 + 1 < 32) asm volatile("cp.async.wait_group 1;\n" ::: "memory");
        else              asm volatile("cp.async.wait_group 0;\n" ::: "memory");
        __syncthreads();

        const uint32_t* S = sm + (t32 & 1) * ASTG;

        float sC[8][4];
#pragma unroll
        for (int j = 0; j < 8; j++)
#pragma unroll
            for (int e = 0; e < 4; e++) sC[j][e] = 0.f;

        // ---- S = Q @ K^T (single pass) ----
#pragma unroll
        for (int t = 0; t < 4; t++) {
#pragma unroll
            for (int jj = 0; jj < 4; jj++) {
                const int j0 = 2*jj, j1 = 2*jj + 1;
                uint32_t b0[2], b1[2];
                b0[0] = S[AKH + (8*t + c)*72     + 8*j0 + rq];
                b0[1] = S[AKH + (8*t + c + 4)*72 + 8*j0 + rq];
                b1[0] = S[AKH + (8*t + c)*72     + 8*j1 + rq];
                b1[1] = S[AKH + (8*t + c + 4)*72 + 8*j1 + rq];
                mma_f16(sC[j0], qh[t], b0);
                mma_f16(sC[j1], qh[t], b1);
            }
        }

        const int wbase = k0 >> 5;
        const uint32_t w00 = MB[(size_t)r0*64 + wbase],     w01 = MB[(size_t)r0*64 + wbase + 1];
        const uint32_t w10 = MB[(size_t)(r0+8)*64 + wbase], w11 = MB[(size_t)(r0+8)*64 + wbase + 1];
        softmax_row(sC, oC, 0, w00, w01, c, mi[0], li[0]);
        softmax_row(sC, oC, 2, w10, w11, c, mi[1], li[1]);

        // ---- O += P @ V (single pass) ----
#pragma unroll
        for (int tp = 0; tp < 4; tp++) {
            uint32_t pah[4];
            pah[0] = pack_h2(sC[2*tp][0],   sC[2*tp][1]);
            pah[1] = pack_h2(sC[2*tp][2],   sC[2*tp][3]);
            pah[2] = pack_h2(sC[2*tp+1][0], sC[2*tp+1][1]);
            pah[3] = pack_h2(sC[2*tp+1][2], sC[2*tp+1][3]);
#pragma unroll
            for (int jj = 0; jj < 4; jj++) {
                const int j0 = 2*jj, j1 = 2*jj + 1;
                uint32_t b0[2], b1[2];
                b0[0] = S[AVH + (8*tp + c)*72     + 8*j0 + rq];
                b0[1] = S[AVH + (8*tp + c + 4)*72 + 8*j0 + rq];
                b1[0] = S[AVH + (8*tp + c)*72     + 8*j1 + rq];
                b1[1] = S[AVH + (8*tp + c + 4)*72 + 8*j1 + rq];
                mma_f16(oC[j0], pah, b0);
                mma_f16(oC[j1], pah, b1);
            }
        }
        __syncthreads();
    }

    // normalize + emit out-proj A operand (single f16)
    const float inv0 = 1.0f / li[0];
    const float inv1 = 1.0f / li[1];
    const size_t mrow = (size_t)b*2048 + r0;
#pragma unroll
    for (int j = 0; j < 8; j++) {
        const int k2 = h*32 + 4*j + c;
        g_oh[mrow*512 + k2]     = pack_h2(oC[j][0]*inv0, oC[j][1]*inv0);
        g_oh[(mrow+8)*512 + k2] = pack_h2(oC[j][2]*inv1, oC[j][3]*inv1);
    }
}

// ---------------------------------------------------------------------------

extern "C" void kernel_launch(void* const* d_in, const int* in_sizes, int n_in,
                              void* d_out, int out_size)
{
    const float* x     = (const float*)d_in[0];
    const int*   mask  = (const int*)  d_in[1];
    const float* W_qkv = (const float*)d_in[2];
    const float* b_qkv = (const float*)d_in[3];
    const float* W_out = (const float*)d_in[4];
    const float* b_out = (const float*)d_in[5];
    float* out = (float*)d_out;

    cudaFuncSetAttribute(gemm_f16x1<0>, cudaFuncAttributeMaxDynamicSharedMemorySize, GEMM_SMEM);
    cudaFuncSetAttribute(gemm_f16x1<1>, cudaFuncAttributeMaxDynamicSharedMemorySize, GEMM_SMEM);
    cudaFuncSetAttribute(attn_mma_kernel, cudaFuncAttributeMaxDynamicSharedMemorySize, ATTN_SMEM);

    uint32_t *xh, *wqh, *oh, *woh;
    cudaGetSymbolAddress((void**)&xh,  g_xh);
    cudaGetSymbolAddress((void**)&wqh, g_wqh);
    cudaGetSymbolAddress((void**)&oh,  g_oh);
    cudaGetSymbolAddress((void**)&woh, g_woh);

    // Operand prep
    conv_A_f16<<<(4096*512)/256, 256>>>(x, xh, 4096*512);
    split_B_f16<<<dim3(3072/256, 512), 256>>>(W_qkv, wqh, 3072);
    maskpack<<<(2*2048*64)/256, 256>>>(mask);

    // QKV projection (f16 single-pass) -> f16 Q / K / V (V pre-repacked)
    gemm_f16x1<0><<<dim3(24, 32), 256, GEMM_SMEM>>>(xh, wqh, b_qkv, nullptr, 3072);

    // Attention (f16 single-pass) -> g_oh (f16)
    attn_mma_kernel<<<dim3(16, 32), 256, ATTN_SMEM>>>();

    // Output projection (f16 single-pass)
    split_B_f16<<<dim3(1024/256, 512), 256>>>(W_out, woh, 1024);
    gemm_f16x1<1><<<dim3(8, 32), 256, GEMM_SMEM>>>(oh, woh, b_out, out, 1024);
}

// round 13
// speedup vs baseline: 2.1502x; 1.0375x over previous
#include <cuda_runtime.h>
#include <cuda_fp16.h>
#include <cstdint>

#define SCALE_ 0.125f   // 1/sqrt(64)

// f16 operands (u32 = packed f16x2 along k-pairs)
__device__ uint32_t g_xh [4096*512];    // X    [M][K/2]
__device__ uint32_t g_wqh[512*3072];    // Wqkv [K/2][N]
__device__ uint32_t g_oh [4096*512];    // attnO[M][K/2]
__device__ uint32_t g_woh[512*1024];    // Wout [K/2][N]

// attention operands (f16)
__device__ uint32_t g_qh [32*2048*32];  // Q [bh][l][dk2]
__device__ uint32_t g_kh [32*32*2048];  // K [bh][dk2][l]
__device__ uint32_t g_vh [32*1024*64];  // V [bh][l2][dk] (pairs along l)
__device__ uint32_t g_mb [2*2048*64];   // mask bits

// ---------------------------------------------------------------------------
// Helpers
// ---------------------------------------------------------------------------
__device__ __forceinline__ uint32_t pack_h2(float a, float b) {
    __half2 h = __floats2half2_rn(a, b);
    return *reinterpret_cast<uint32_t*>(&h);
}
__device__ __forceinline__ uint16_t f16bits(float a) {
    __half h = __float2half_rn(a);
    return *reinterpret_cast<uint16_t*>(&h);
}
__device__ __forceinline__ void cp16(uint32_t saddr, const void* gptr) {
    asm volatile("cp.async.cg.shared.global [%0], [%1], 16;\n" :: "r"(saddr), "l"(gptr));
}
__device__ __forceinline__ void cp_commit() {
    asm volatile("cp.async.commit_group;\n" ::: "memory");
}
__device__ __forceinline__ void mma_f16(float* c, const uint32_t* a, const uint32_t* b) {
    asm volatile(
        "mma.sync.aligned.m16n8k16.row.col.f32.f16.f16.f32 "
        "{%0,%1,%2,%3}, {%4,%5,%6,%7}, {%8,%9}, {%0,%1,%2,%3};\n"
        : "+f"(c[0]), "+f"(c[1]), "+f"(c[2]), "+f"(c[3])
        : "r"(a[0]), "r"(a[1]), "r"(a[2]), "r"(a[3]), "r"(b[0]), "r"(b[1]));
}

// ---------------------------------------------------------------------------
// Operand prep kernels
// ---------------------------------------------------------------------------
__global__ void conv_A_f16(const float* __restrict__ in,
                           uint32_t* __restrict__ h, int n)
{
    int i = blockIdx.x * blockDim.x + threadIdx.x;
    if (i >= n) return;
    float2 a = ((const float2*)in)[i];
    h[i] = pack_h2(a.x, a.y);
}

__global__ void split_B_f16(const float* __restrict__ in,
                            uint32_t* __restrict__ h, int N)
{
    int n  = blockIdx.x * blockDim.x + threadIdx.x;
    int k2 = blockIdx.y;
    float a0 = in[(size_t)(2*k2)   * N + n];
    float a1 = in[(size_t)(2*k2+1) * N + n];
    h[(size_t)k2 * N + n] = pack_h2(a0, a1);
}

__global__ void maskpack(const int* __restrict__ mask)
{
    int idx = blockIdx.x * 256 + threadIdx.x;
    int w   = idx & 63;
    int row = idx >> 6;
    const int4* p = (const int4*)(mask + (size_t)row * 2048 + w * 32);
    uint32_t bits = 0;
#pragma unroll
    for (int i = 0; i < 8; i++) {
        int4 v = p[i];
        bits |= (uint32_t)(v.x != 0) << (4*i)
             |  (uint32_t)(v.y != 0) << (4*i+1)
             |  (uint32_t)(v.z != 0) << (4*i+2)
             |  (uint32_t)(v.w != 0) << (4*i+3);
    }
    g_mb[idx] = bits;
}

// ---------------------------------------------------------------------------
// f16 single-pass GEMM: 1 MMA per k16. Block 128x128, K-tile 32,
// 512 threads (16 warps, warp 32x32) for latency hiding.
// EPI=0: QKV epilogue -> f16 Q / K / V (V directly in [l2][dk] pair layout).
// EPI=1: plain f32 write + bias.
// ---------------------------------------------------------------------------
#define OA  0
#define OB  2560
#define STG 4736
#define GEMM_SMEM (2*STG*4)   // 37888 B

template<int EPI>
__global__ void __launch_bounds__(512, 1)
gemm_f16x1(const uint32_t* __restrict__ Ah,
           const uint32_t* __restrict__ Bh,
           const float* __restrict__ bias, float* __restrict__ outp, int N)
{
    extern __shared__ uint32_t sm[];
    const int tid  = threadIdx.x;
    const int lane = tid & 31;
    const int wid  = tid >> 5;
    const int wm   = wid >> 2;      // 0..3 -> 32-row band
    const int wn   = wid & 3;       // 0..3 -> 32-col band
    const int rq   = lane >> 2;
    const int m0   = blockIdx.y * 128;
    const int n0   = blockIdx.x * 128;
    const int KP2  = 512;

    const uint32_t sbase = (uint32_t)__cvta_generic_to_shared(sm);

    float C[2][4][4];
#pragma unroll
    for (int mt = 0; mt < 2; mt++)
#pragma unroll
        for (int nt = 0; nt < 4; nt++)
#pragma unroll
            for (int e = 0; e < 4; e++) C[mt][nt][e] = 0.f;

    auto load_stage = [&](int s, int kp0) {
        uint32_t sa = sbase + (uint32_t)(s * STG) * 4;
        {
            const int row = tid >> 2, c4 = (tid & 3) << 2;
            cp16(sa + (OA + row*20 + c4)*4, Ah + (size_t)(m0+row)*KP2 + kp0 + c4);
        }
        {
            const int row = tid >> 5, c4 = (tid & 31) << 2;
            cp16(sa + (OB + row*136 + c4)*4, Bh + (size_t)(kp0+row)*N + n0 + c4);
        }
    };

    load_stage(0, 0);
    cp_commit();

    const int T = 32;
    for (int t = 0; t < T; t++) {
        if (t + 1 < T) { load_stage((t+1)&1, (t+1)*16); cp_commit(); }
        if (t + 1 < T) asm volatile("cp.async.wait_group 1;\n" ::: "memory");
        else           asm volatile("cp.async.wait_group 0;\n" ::: "memory");
        __syncthreads();

        const uint32_t* S = sm + (t & 1) * STG;
#pragma unroll
        for (int ss = 0; ss < 2; ss++) {
            const int c2 = ss*8 + (lane & 3);
            uint32_t ah[2][4];
#pragma unroll
            for (int mt = 0; mt < 2; mt++) {
                const int r0 = wm*32 + mt*16 + rq;
                ah[mt][0] = S[OA + r0*20 + c2];
                ah[mt][1] = S[OA + (r0+8)*20 + c2];
                ah[mt][2] = S[OA + r0*20 + c2 + 4];
                ah[mt][3] = S[OA + (r0+8)*20 + c2 + 4];
            }
            uint32_t bh[4][2];
#pragma unroll
            for (int nt = 0; nt < 4; nt++) {
                const int col = wn*32 + nt*8 + rq;
                bh[nt][0] = S[OB + c2*136 + col];
                bh[nt][1] = S[OB + (c2+4)*136 + col];
            }
#pragma unroll
            for (int mt = 0; mt < 2; mt++)
#pragma unroll
                for (int nt = 0; nt < 4; nt++)
                    mma_f16(C[mt][nt], ah[mt], bh[nt]);
        }
        __syncthreads();
    }

    // Epilogue
#pragma unroll
    for (int mt = 0; mt < 2; mt++) {
#pragma unroll
        for (int nt = 0; nt < 4; nt++) {
            const int r = m0 + wm*32 + mt*16 + rq;
            const int c = n0 + wn*32 + nt*8 + (lane & 3)*2;
            const float b0 = bias[c], b1 = bias[c+1];
            const float v00 = C[mt][nt][0]+b0, v01 = C[mt][nt][1]+b1;
            const float v10 = C[mt][nt][2]+b0, v11 = C[mt][nt][3]+b1;
            if (EPI == 0) {
                const int part = c >> 10;
                const int d0  = c & 1023;
                const int h   = d0 >> 6;
                const int d   = d0 & 63;
                const int dk2 = d >> 1;
                const int bI  = r >> 11;
                const int l   = r & 2047;
                const int bh  = bI*16 + h;
                if (part == 0) {
                    size_t i0 = ((size_t)bh*2048 + l)*32 + dk2;
                    g_qh[i0]        = pack_h2(v00, v01);
                    g_qh[i0 + 8*32] = pack_h2(v10, v11);
                } else if (part == 1) {
                    size_t i0 = ((size_t)bh*32 + dk2)*2048 + l;
                    g_kh[i0]     = pack_h2(v00, v01);
                    g_kh[i0 + 8] = pack_h2(v10, v11);
                } else {
                    uint16_t* V16 = (uint16_t*)g_vh;
                    const int p  = l & 1;
                    const int l2 = l >> 1;
                    size_t base0 = (((size_t)bh*1024 + l2    )*64 + d)*2 + p;
                    size_t base1 = (((size_t)bh*1024 + l2 + 4)*64 + d)*2 + p;
                    V16[base0]     = f16bits(v00);
                    V16[base0 + 2] = f16bits(v01);
                    V16[base1]     = f16bits(v10);
                    V16[base1 + 2] = f16bits(v11);
                }
            } else {
                *(float2*)&outp[(size_t)r*N + c]     = make_float2(v00, v01);
                *(float2*)&outp[(size_t)(r+8)*N + c] = make_float2(v10, v11);
            }
        }
    }
}

// ---------------------------------------------------------------------------
// f16 single-pass flash attention: 128 queries/CTA, 8 warps, 2 CTAs/SM.
// ---------------------------------------------------------------------------
#define AKH 0
#define AVH 2304
#define ASTG 4608
#define ATTN_SMEM (2*ASTG*4)   // 36864 bytes

__device__ __forceinline__ void softmax_row(float (&sC)[8][4], float (&oC)[8][4],
                                            int e0, uint32_t w0, uint32_t w1,
                                            int c, float& mi, float& li)
{
    float rm = -1e30f;
    uint32_t rbits = 0;
#pragma unroll
    for (int j = 0; j < 8; j++) {
        const uint32_t w = (j < 4) ? w0 : w1;
#pragma unroll
        for (int e = 0; e < 2; e++) {
            const int col = 8*j + 2*c + e;
            const uint32_t bit = (w >> (col & 31)) & 1u;
            const float sv = bit ? sC[j][e0+e]*SCALE_ : 0.f;
            sC[j][e0+e] = sv;
            rbits |= bit << (2*j + e);
            rm = fmaxf(rm, sv);
        }
    }
    rm = fmaxf(rm, __shfl_xor_sync(0xffffffffu, rm, 1));
    rm = fmaxf(rm, __shfl_xor_sync(0xffffffffu, rm, 2));
    const float mn  = fmaxf(mi, rm);
    const float fac = __expf(mi - mn);
    float rs = 0.f;
#pragma unroll
    for (int j = 0; j < 8; j++)
#pragma unroll
        for (int e = 0; e < 2; e++) {
            const float pd = __expf(sC[j][e0+e] - mn);
            rs += pd;
            sC[j][e0+e] = ((rbits >> (2*j + e)) & 1u) ? pd : 0.f;
        }
    rs += __shfl_xor_sync(0xffffffffu, rs, 1);
    rs += __shfl_xor_sync(0xffffffffu, rs, 2);
    li = li*fac + rs;
    mi = mn;
#pragma unroll
    for (int j = 0; j < 8; j++) { oC[j][e0] *= fac; oC[j][e0+1] *= fac; }
}

__global__ void __launch_bounds__(256, 2)
attn_mma_kernel()
{
    extern __shared__ uint32_t sm[];
    const int tid  = threadIdx.x;
    const int lane = tid & 31;
    const int wid  = tid >> 5;
    const int c    = lane & 3;
    const int rq   = lane >> 2;
    const int bh   = blockIdx.y;
    const int b    = bh >> 4;
    const int h    = bh & 15;
    const int q0   = blockIdx.x * 128;
    const int r0   = q0 + wid*16 + rq;

    const uint32_t sbase = (uint32_t)__cvta_generic_to_shared(sm);

    uint32_t qh[4][4];
    {
        const uint32_t* Qh = g_qh + (size_t)bh*2048*32;
#pragma unroll
        for (int t = 0; t < 4; t++) {
            qh[t][0] = Qh[(size_t)r0*32     + 8*t + c];
            qh[t][1] = Qh[(size_t)(r0+8)*32 + 8*t + c];
            qh[t][2] = Qh[(size_t)r0*32     + 8*t + c + 4];
            qh[t][3] = Qh[(size_t)(r0+8)*32 + 8*t + c + 4];
        }
    }

    float oC[8][4];
#pragma unroll
    for (int j = 0; j < 8; j++)
#pragma unroll
        for (int e = 0; e < 4; e++) oC[j][e] = 0.f;
    float mi[2] = {-1e30f, -1e30f};
    float li[2] = {0.f, 0.f};

    auto load_stage = [&](int s, int k0) {
        const uint32_t sa = sbase + (uint32_t)(s * ASTG) * 4;
#pragma unroll
        for (int it = 0; it < 2; it++) {
            const int idx = it*256 + tid;
            const int row = idx >> 4;
            const int c4  = (idx & 15) * 4;
            cp16(sa + (AKH + row*72 + c4)*4, g_kh + ((size_t)bh*32 + row)*2048 + k0 + c4);
            cp16(sa + (AVH + row*72 + c4)*4, g_vh + ((size_t)bh*1024 + (k0>>1) + row)*64 + c4);
        }
    };

    load_stage(0, 0);
    cp_commit();

    const uint32_t* MB = g_mb + (size_t)b*2048*64;

    for (int t32 = 0; t32 < 32; t32++) {
        const int k0 = t32 * 64;
        if (t32 + 1 < 32) { load_stage((t32+1)&1, k0 + 64); cp_commit(); }
        if (t32 + 1 < 32) asm volatile("cp.async.wait_group 1;\n" ::: "memory");
        else              asm volatile("cp.async.wait_group 0;\n" ::: "memory");
        __syncthreads();

        const uint32_t* S = sm + (t32 & 1) * ASTG;

        float sC[8][4];
#pragma unroll
        for (int j = 0; j < 8; j++)
#pragma unroll
            for (int e = 0; e < 4; e++) sC[j][e] = 0.f;

        // ---- S = Q @ K^T (single pass) ----
#pragma unroll
        for (int t = 0; t < 4; t++) {
#pragma unroll
            for (int jj = 0; jj < 4; jj++) {
                const int j0 = 2*jj, j1 = 2*jj + 1;
                uint32_t b0[2], b1[2];
                b0[0] = S[AKH + (8*t + c)*72     + 8*j0 + rq];
                b0[1] = S[AKH + (8*t + c + 4)*72 + 8*j0 + rq];
                b1[0] = S[AKH + (8*t + c)*72     + 8*j1 + rq];
                b1[1] = S[AKH + (8*t + c + 4)*72 + 8*j1 + rq];
                mma_f16(sC[j0], qh[t], b0);
                mma_f16(sC[j1], qh[t], b1);
            }
        }

        const int wbase = k0 >> 5;
        const uint32_t w00 = MB[(size_t)r0*64 + wbase],     w01 = MB[(size_t)r0*64 + wbase + 1];
        const uint32_t w10 = MB[(size_t)(r0+8)*64 + wbase], w11 = MB[(size_t)(r0+8)*64 + wbase + 1];
        softmax_row(sC, oC, 0, w00, w01, c, mi[0], li[0]);
        softmax_row(sC, oC, 2, w10, w11, c, mi[1], li[1]);

        // ---- O += P @ V (single pass) ----
#pragma unroll
        for (int tp = 0; tp < 4; tp++) {
            uint32_t pah[4];
            pah[0] = pack_h2(sC[2*tp][0],   sC[2*tp][1]);
            pah[1] = pack_h2(sC[2*tp][2],   sC[2*tp][3]);
            pah[2] = pack_h2(sC[2*tp+1][0], sC[2*tp+1][1]);
            pah[3] = pack_h2(sC[2*tp+1][2], sC[2*tp+1][3]);
#pragma unroll
            for (int jj = 0; jj < 4; jj++) {
                const int j0 = 2*jj, j1 = 2*jj + 1;
                uint32_t b0[2], b1[2];
                b0[0] = S[AVH + (8*tp + c)*72     + 8*j0 + rq];
                b0[1] = S[AVH + (8*tp + c + 4)*72 + 8*j0 + rq];
                b1[0] = S[AVH + (8*tp + c)*72     + 8*j1 + rq];
                b1[1] = S[AVH + (8*tp + c + 4)*72 + 8*j1 + rq];
                mma_f16(oC[j0], pah, b0);
                mma_f16(oC[j1], pah, b1);
            }
        }
        __syncthreads();
    }

    // normalize + emit out-proj A operand (single f16)
    const float inv0 = 1.0f / li[0];
    const float inv1 = 1.0f / li[1];
    const size_t mrow = (size_t)b*2048 + r0;
#pragma unroll
    for (int j = 0; j < 8; j++) {
        const int k2 = h*32 + 4*j + c;
        g_oh[mrow*512 + k2]     = pack_h2(oC[j][0]*inv0, oC[j][1]*inv0);
        g_oh[(mrow+8)*512 + k2] = pack_h2(oC[j][2]*inv1, oC[j][3]*inv1);
    }
}

// ---------------------------------------------------------------------------

extern "C" void kernel_launch(void* const* d_in, const int* in_sizes, int n_in,
                              void* d_out, int out_size)
{
    const float* x     = (const float*)d_in[0];
    const int*   mask  = (const int*)  d_in[1];
    const float* W_qkv = (const float*)d_in[2];
    const float* b_qkv = (const float*)d_in[3];
    const float* W_out = (const float*)d_in[4];
    const float* b_out = (const float*)d_in[5];
    float* out = (float*)d_out;

    cudaFuncSetAttribute(gemm_f16x1<0>, cudaFuncAttributeMaxDynamicSharedMemorySize, GEMM_SMEM);
    cudaFuncSetAttribute(gemm_f16x1<1>, cudaFuncAttributeMaxDynamicSharedMemorySize, GEMM_SMEM);
    cudaFuncSetAttribute(attn_mma_kernel, cudaFuncAttributeMaxDynamicSharedMemorySize, ATTN_SMEM);

    uint32_t *xh, *wqh, *oh, *woh;
    cudaGetSymbolAddress((void**)&xh,  g_xh);
    cudaGetSymbolAddress((void**)&wqh, g_wqh);
    cudaGetSymbolAddress((void**)&oh,  g_oh);
    cudaGetSymbolAddress((void**)&woh, g_woh);

    // Operand prep
    conv_A_f16<<<(4096*512)/256, 256>>>(x, xh, 4096*512);
    split_B_f16<<<dim3(3072/256, 512), 256>>>(W_qkv, wqh, 3072);
    maskpack<<<(2*2048*64)/256, 256>>>(mask);

    // QKV projection (f16 single-pass, 512 thr) -> f16 Q / K / V
    gemm_f16x1<0><<<dim3(24, 32), 512, GEMM_SMEM>>>(xh, wqh, b_qkv, nullptr, 3072);

    // Attention (f16 single-pass, 2 CTAs/SM) -> g_oh (f16)
    attn_mma_kernel<<<dim3(16, 32), 256, ATTN_SMEM>>>();

    // Output projection (f16 single-pass, 512 thr)
    split_B_f16<<<dim3(1024/256, 512), 256>>>(W_out, woh, 1024);
    gemm_f16x1<1><<<dim3(8, 32), 512, GEMM_SMEM>>>(oh, woh, b_out, out, 1024);
}

// round 14
// speedup vs baseline: 2.6472x; 1.2311x over previous
#include <cuda_runtime.h>
#include <cuda_fp16.h>
#include <cstdint>

#define SCALE_ 0.125f   // 1/sqrt(64)

// Fragment-packed f16 operands.
// A-type: [m16blk][k16chunk(64)][lane(32)][4 u32]   (one LDS.128 per fragment)
// B-type: [k16chunk][n][c(4)][2 u32]                (one LDS.64 per fragment)
__device__ uint32_t g_xh [4096/16*64*32*4];   // X packed     (= 4096*512)
__device__ uint32_t g_wqh[64*3072*8];         // Wqkv packed  (= 512*3072)
__device__ uint32_t g_oh [4096/16*64*32*4];   // attnO packed
__device__ uint32_t g_woh[64*1024*8];         // Wout packed

// attention operands
__device__ uint32_t g_qh [32*2048*32];        // Q [bh][l][dk2] (reg gather, unchanged)
__device__ uint32_t g_kh [32*4*2048*8];       // K packed: [bh][t(4)][key(2048)][c(4)][2]
__device__ uint32_t g_vh [32*32*4*64*8];      // V packed: [bh][T(32)][tp(4)][dk(64)][c(4)][2]
__device__ uint32_t g_mb [2*2048*64];         // mask bits

// ---------------------------------------------------------------------------
// Helpers
// ---------------------------------------------------------------------------
__device__ __forceinline__ uint32_t pack_h2(float a, float b) {
    __half2 h = __floats2half2_rn(a, b);
    return *reinterpret_cast<uint32_t*>(&h);
}
__device__ __forceinline__ uint16_t f16bits(float a) {
    __half h = __float2half_rn(a);
    return *reinterpret_cast<uint16_t*>(&h);
}
__device__ __forceinline__ void cp16(uint32_t saddr, const void* gptr) {
    asm volatile("cp.async.cg.shared.global [%0], [%1], 16;\n" :: "r"(saddr), "l"(gptr));
}
__device__ __forceinline__ void cp_commit() {
    asm volatile("cp.async.commit_group;\n" ::: "memory");
}
__device__ __forceinline__ void mma_f16(float* c, const uint32_t* a, const uint32_t* b) {
    asm volatile(
        "mma.sync.aligned.m16n8k16.row.col.f32.f16.f16.f32 "
        "{%0,%1,%2,%3}, {%4,%5,%6,%7}, {%8,%9}, {%0,%1,%2,%3};\n"
        : "+f"(c[0]), "+f"(c[1]), "+f"(c[2]), "+f"(c[3])
        : "r"(a[0]), "r"(a[1]), "r"(a[2]), "r"(a[3]), "r"(b[0]), "r"(b[1]));
}

// V u16 index: value at (key l, dk d) in packed V
__device__ __forceinline__ size_t vidx16(int bh, int l, int d) {
    const int l2 = l >> 1, p = l & 1;
    const int T = l2 >> 5, rem = l2 & 31;
    const int tp = rem >> 3, cr = rem & 7;
    size_t u = (((size_t)(bh*32 + T)*4 + tp)*64 + d)*8 + (cr & 3)*2 + (cr >> 2);
    return u*2 + p;
}

// ---------------------------------------------------------------------------
// Operand prep kernels
// ---------------------------------------------------------------------------
// x [4096][1024] f32 -> A-packed g_xh. One thread per (mb, kc, lane).
__global__ void conv_A_pack(const float* __restrict__ in, uint32_t* __restrict__ outp)
{
    const int i  = blockIdx.x * 256 + threadIdx.x;   // 0 .. 524287
    const int l  = i & 31;
    const int kc = (i >> 5) & 63;
    const int mb = i >> 11;
    const int rq = l >> 2, c = l & 3;
    const float2* x2 = (const float2*)in;
    const size_t row0 = (size_t)(mb*16 + rq) * 512;
    const size_t row1 = row0 + 8*512;
    float2 a0 = x2[row0 + kc*8 + c];
    float2 a1 = x2[row1 + kc*8 + c];
    float2 a2 = x2[row0 + kc*8 + c + 4];
    float2 a3 = x2[row1 + kc*8 + c + 4];
    uint4 v;
    v.x = pack_h2(a0.x, a0.y);
    v.y = pack_h2(a1.x, a1.y);
    v.z = pack_h2(a2.x, a2.y);
    v.w = pack_h2(a3.x, a3.y);
    ((uint4*)outp)[i] = v;
}

// W [1024][N] f32 -> B-packed. One thread per (kc, c, n).
__global__ void split_B_pack(const float* __restrict__ in, uint32_t* __restrict__ outp, int N)
{
    const int i = blockIdx.x * 256 + threadIdx.x;    // 0 .. 64*4*N-1
    const int n  = i % N;
    const int c  = (i / N) & 3;
    const int kc = i / (4*N);
    const int k2a = kc*8 + c;
    const int k2b = k2a + 4;
    uint2 v;
    v.x = pack_h2(in[(size_t)(2*k2a)*N + n], in[(size_t)(2*k2a+1)*N + n]);
    v.y = pack_h2(in[(size_t)(2*k2b)*N + n], in[(size_t)(2*k2b+1)*N + n]);
    ((uint2*)outp)[((size_t)kc*N + n)*4 + c] = v;
}

__global__ void maskpack(const int* __restrict__ mask)
{
    int idx = blockIdx.x * 256 + threadIdx.x;
    int w   = idx & 63;
    int row = idx >> 6;
    const int4* p = (const int4*)(mask + (size_t)row * 2048 + w * 32);
    uint32_t bits = 0;
#pragma unroll
    for (int i = 0; i < 8; i++) {
        int4 v = p[i];
        bits |= (uint32_t)(v.x != 0) << (4*i)
             |  (uint32_t)(v.y != 0) << (4*i+1)
             |  (uint32_t)(v.z != 0) << (4*i+2)
             |  (uint32_t)(v.w != 0) << (4*i+3);
    }
    g_mb[idx] = bits;
}

// ---------------------------------------------------------------------------
// f16 single-pass GEMM, fragment-packed operands.
// Block 128x128, K-tile 32, 256 threads (8 warps, warp 64x32).
// Per ss: 4 LDS.128 (A) + 4 LDS.64 (B) feed 16 MMAs.
// ---------------------------------------------------------------------------
#define OA  0
#define OB  2048
#define STG 4096
#define GEMM_SMEM (2*STG*4)   // 32768 B

template<int EPI>
__global__ void __launch_bounds__(256, 2)
gemm_f16x1(const uint32_t* __restrict__ Ah,
           const uint32_t* __restrict__ Bh,
           const float* __restrict__ bias, float* __restrict__ outp, int N)
{
    extern __shared__ uint32_t sm[];
    const int tid  = threadIdx.x;
    const int lane = tid & 31;
    const int wid  = tid >> 5;
    const int wm   = wid >> 2;      // 0..1 -> 64-row band
    const int wn   = wid & 3;       // 0..3 -> 32-col band
    const int rq   = lane >> 2;
    const int cL   = lane & 3;
    const int m0   = blockIdx.y * 128;
    const int n0   = blockIdx.x * 128;
    const int mb0  = m0 >> 4;

    const uint32_t sbase = (uint32_t)__cvta_generic_to_shared(sm);

    float C[4][4][4];
#pragma unroll
    for (int mt = 0; mt < 4; mt++)
#pragma unroll
        for (int nt = 0; nt < 4; nt++)
#pragma unroll
            for (int e = 0; e < 4; e++) C[mt][nt][e] = 0.f;

    auto load_stage = [&](int s, int t) {
        const uint32_t sa = sbase + (uint32_t)(s * STG) * 4;
        const int kc0 = 2*t;
#pragma unroll
        for (int it = 0; it < 2; it++) {     // A: 512 chunks
            const int j = it*256 + tid;
            const int mbL = j >> 6, kcL = (j >> 5) & 1, l = j & 31;
            cp16(sa + (OA + j*4)*4,
                 Ah + ((size_t)(mb0 + mbL)*64 + kc0 + kcL)*128 + l*4);
        }
#pragma unroll
        for (int it = 0; it < 2; it++) {     // B: 512 chunks
            const int j = it*256 + tid;
            const int kcL = j >> 8, nLoc = (j >> 1) & 127, q = j & 1;
            cp16(sa + (OB + (kcL*128 + nLoc)*8 + q*4)*4,
                 Bh + ((size_t)(kc0 + kcL)*N + n0 + nLoc)*8 + q*4);
        }
        cp_commit();
    };

    load_stage(0, 0);

    const int T = 32;
    for (int t = 0; t < T; t++) {
        if (t + 1 < T) { load_stage((t+1)&1, t+1); }
        if (t + 1 < T) asm volatile("cp.async.wait_group 1;\n" ::: "memory");
        else           asm volatile("cp.async.wait_group 0;\n" ::: "memory");
        __syncthreads();

        const uint32_t* S = sm + (t & 1) * STG;
#pragma unroll
        for (int ss = 0; ss < 2; ss++) {
            uint4 av[4];
#pragma unroll
            for (int mt = 0; mt < 4; mt++)
                av[mt] = *(const uint4*)&S[OA + (((wm*4 + mt)*2 + ss)*32 + lane)*4];
            uint2 bv[4];
#pragma unroll
            for (int nt = 0; nt < 4; nt++)
                bv[nt] = *(const uint2*)&S[OB + ((ss*128 + wn*32 + nt*8 + rq)*4 + cL)*2];
#pragma unroll
            for (int mt = 0; mt < 4; mt++)
#pragma unroll
                for (int nt = 0; nt < 4; nt++)
                    mma_f16(C[mt][nt], (const uint32_t*)&av[mt], (const uint32_t*)&bv[nt]);
        }
        __syncthreads();
    }

    // Epilogue
#pragma unroll
    for (int mt = 0; mt < 4; mt++) {
#pragma unroll
        for (int nt = 0; nt < 4; nt++) {
            const int r = m0 + wm*64 + mt*16 + rq;
            const int c = n0 + wn*32 + nt*8 + cL*2;
            const float b0 = bias[c], b1 = bias[c+1];
            const float v00 = C[mt][nt][0]+b0, v01 = C[mt][nt][1]+b1;
            const float v10 = C[mt][nt][2]+b0, v11 = C[mt][nt][3]+b1;
            if (EPI == 0) {
                const int part = c >> 10;
                const int d0  = c & 1023;
                const int h   = d0 >> 6;
                const int d   = d0 & 63;
                const int dk2 = d >> 1;
                const int bI  = r >> 11;
                const int l   = r & 2047;
                const int bh  = bI*16 + h;
                if (part == 0) {
                    size_t i0 = ((size_t)bh*2048 + l)*32 + dk2;
                    g_qh[i0]        = pack_h2(v00, v01);
                    g_qh[i0 + 8*32] = pack_h2(v10, v11);
                } else if (part == 1) {
                    const int tK = dk2 >> 3, cc = dk2 & 7;
                    size_t ki = ((size_t)(bh*4 + tK)*2048 + l)*8 + (cc & 3)*2 + (cc >> 2);
                    g_kh[ki]      = pack_h2(v00, v01);
                    g_kh[ki + 64] = pack_h2(v10, v11);   // key l+8
                } else {
                    uint16_t* V16 = (uint16_t*)g_vh;
                    size_t i0 = vidx16(bh, l, d);
                    size_t i1 = vidx16(bh, l + 8, d);
                    V16[i0]      = f16bits(v00);
                    V16[i0 + 16] = f16bits(v01);         // d+1 -> +8 u32 -> +16 u16
                    V16[i1]      = f16bits(v10);
                    V16[i1 + 16] = f16bits(v11);
                }
            } else {
                *(float2*)&outp[(size_t)r*N + c]     = make_float2(v00, v01);
                *(float2*)&outp[(size_t)(r+8)*N + c] = make_float2(v10, v11);
            }
        }
    }
}

// ---------------------------------------------------------------------------
// f16 single-pass flash attention, fragment-packed K/V. 128 queries/CTA,
// 8 warps, 2 CTAs/SM. 1 LDS.64 per MMA.
// ---------------------------------------------------------------------------
#define AKH 0
#define AVH 2048
#define ASTG 4096
#define ATTN_SMEM (2*ASTG*4)   // 32768 bytes

__device__ __forceinline__ void softmax_row(float (&sC)[8][4], float (&oC)[8][4],
                                            int e0, uint32_t w0, uint32_t w1,
                                            int c, float& mi, float& li)
{
    float rm = -1e30f;
    uint32_t rbits = 0;
#pragma unroll
    for (int j = 0; j < 8; j++) {
        const uint32_t w = (j < 4) ? w0 : w1;
#pragma unroll
        for (int e = 0; e < 2; e++) {
            const int col = 8*j + 2*c + e;
            const uint32_t bit = (w >> (col & 31)) & 1u;
            const float sv = bit ? sC[j][e0+e]*SCALE_ : 0.f;
            sC[j][e0+e] = sv;
            rbits |= bit << (2*j + e);
            rm = fmaxf(rm, sv);
        }
    }
    rm = fmaxf(rm, __shfl_xor_sync(0xffffffffu, rm, 1));
    rm = fmaxf(rm, __shfl_xor_sync(0xffffffffu, rm, 2));
    const float mn  = fmaxf(mi, rm);
    const float fac = __expf(mi - mn);
    float rs = 0.f;
#pragma unroll
    for (int j = 0; j < 8; j++)
#pragma unroll
        for (int e = 0; e < 2; e++) {
            const float pd = __expf(sC[j][e0+e] - mn);
            rs += pd;
            sC[j][e0+e] = ((rbits >> (2*j + e)) & 1u) ? pd : 0.f;
        }
    rs += __shfl_xor_sync(0xffffffffu, rs, 1);
    rs += __shfl_xor_sync(0xffffffffu, rs, 2);
    li = li*fac + rs;
    mi = mn;
#pragma unroll
    for (int j = 0; j < 8; j++) { oC[j][e0] *= fac; oC[j][e0+1] *= fac; }
}

__global__ void __launch_bounds__(256, 2)
attn_mma_kernel()
{
    extern __shared__ uint32_t sm[];
    const int tid  = threadIdx.x;
    const int lane = tid & 31;
    const int wid  = tid >> 5;
    const int c    = lane & 3;
    const int rq   = lane >> 2;
    const int bh   = blockIdx.y;
    const int b    = bh >> 4;
    const int h    = bh & 15;
    const int q0   = blockIdx.x * 128;
    const int r0   = q0 + wid*16 + rq;

    const uint32_t sbase = (uint32_t)__cvta_generic_to_shared(sm);

    uint32_t qh[4][4];
    {
        const uint32_t* Qh = g_qh + (size_t)bh*2048*32;
#pragma unroll
        for (int t = 0; t < 4; t++) {
            qh[t][0] = Qh[(size_t)r0*32     + 8*t + c];
            qh[t][1] = Qh[(size_t)(r0+8)*32 + 8*t + c];
            qh[t][2] = Qh[(size_t)r0*32     + 8*t + c + 4];
            qh[t][3] = Qh[(size_t)(r0+8)*32 + 8*t + c + 4];
        }
    }

    float oC[8][4];
#pragma unroll
    for (int j = 0; j < 8; j++)
#pragma unroll
        for (int e = 0; e < 4; e++) oC[j][e] = 0.f;
    float mi[2] = {-1e30f, -1e30f};
    float li[2] = {0.f, 0.f};

    auto load_stage = [&](int s, int k0) {
        const uint32_t sa = sbase + (uint32_t)(s * ASTG) * 4;
        const int T = k0 >> 6;
#pragma unroll
        for (int it = 0; it < 2; it++) {     // K: 512 chunks
            const int j = it*256 + tid;
            const int t = j >> 7, keyL = (j >> 1) & 63, q = j & 1;
            cp16(sa + (AKH + t*512 + keyL*8 + q*4)*4,
                 g_kh + ((size_t)(bh*4 + t)*2048 + k0 + keyL)*8 + q*4);
        }
#pragma unroll
        for (int it = 0; it < 2; it++) {     // V: 512 chunks
            const int j = it*256 + tid;
            const int tp = j >> 7, dk = (j >> 1) & 63, q = j & 1;
            cp16(sa + (AVH + tp*512 + dk*8 + q*4)*4,
                 g_vh + (((size_t)(bh*32 + T)*4 + tp)*64 + dk)*8 + q*4);
        }
    };

    load_stage(0, 0);
    cp_commit();

    const uint32_t* MB = g_mb + (size_t)b*2048*64;

    for (int t32 = 0; t32 < 32; t32++) {
        const int k0 = t32 * 64;
        if (t32 + 1 < 32) { load_stage((t32+1)&1, k0 + 64); cp_commit(); }
        if (t32 + 1 < 32) asm volatile("cp.async.wait_group 1;\n" ::: "memory");
        else              asm volatile("cp.async.wait_group 0;\n" ::: "memory");
        __syncthreads();

        const uint32_t* S = sm + (t32 & 1) * ASTG;

        float sC[8][4];
#pragma unroll
        for (int j = 0; j < 8; j++)
#pragma unroll
            for (int e = 0; e < 4; e++) sC[j][e] = 0.f;

        // ---- S = Q @ K^T ----
#pragma unroll
        for (int t = 0; t < 4; t++) {
#pragma unroll
            for (int jj = 0; jj < 4; jj++) {
                const int j0 = 2*jj, j1 = 2*jj + 1;
                uint2 B0 = *(const uint2*)&S[AKH + ((t*64 + 8*j0 + rq)*4 + c)*2];
                uint2 B1 = *(const uint2*)&S[AKH + ((t*64 + 8*j1 + rq)*4 + c)*2];
                mma_f16(sC[j0], qh[t], (const uint32_t*)&B0);
                mma_f16(sC[j1], qh[t], (const uint32_t*)&B1);
            }
        }

        const int wbase = k0 >> 5;
        const uint32_t w00 = MB[(size_t)r0*64 + wbase],     w01 = MB[(size_t)r0*64 + wbase + 1];
        const uint32_t w10 = MB[(size_t)(r0+8)*64 + wbase], w11 = MB[(size_t)(r0+8)*64 + wbase + 1];
        softmax_row(sC, oC, 0, w00, w01, c, mi[0], li[0]);
        softmax_row(sC, oC, 2, w10, w11, c, mi[1], li[1]);

        // ---- O += P @ V ----
#pragma unroll
        for (int tp = 0; tp < 4; tp++) {
            uint32_t pah[4];
            pah[0] = pack_h2(sC[2*tp][0],   sC[2*tp][1]);
            pah[1] = pack_h2(sC[2*tp][2],   sC[2*tp][3]);
            pah[2] = pack_h2(sC[2*tp+1][0], sC[2*tp+1][1]);
            pah[3] = pack_h2(sC[2*tp+1][2], sC[2*tp+1][3]);
#pragma unroll
            for (int jj = 0; jj < 4; jj++) {
                const int j0 = 2*jj, j1 = 2*jj + 1;
                uint2 B0 = *(const uint2*)&S[AVH + ((tp*64 + 8*j0 + rq)*4 + c)*2];
                uint2 B1 = *(const uint2*)&S[AVH + ((tp*64 + 8*j1 + rq)*4 + c)*2];
                mma_f16(oC[j0], pah, (const uint32_t*)&B0);
                mma_f16(oC[j1], pah, (const uint32_t*)&B1);
            }
        }
        __syncthreads();
    }

    // normalize + emit out-proj A operand in A-packed layout
    const float inv0 = 1.0f / li[0];
    const float inv1 = 1.0f / li[1];
    const size_t mrow = (size_t)b*2048 + r0;
    const size_t mb = mrow >> 4;
#pragma unroll
    for (int j = 0; j < 8; j++) {
        const int kc = h*4 + (j >> 1);
        const size_t base = ((mb*64 + kc)*32 + rq*4 + c)*4 + (j & 1)*2;
        g_oh[base]     = pack_h2(oC[j][0]*inv0, oC[j][1]*inv0);   // row rq
        g_oh[base + 1] = pack_h2(oC[j][2]*inv1, oC[j][3]*inv1);   // row rq+8
    }
}

// ---------------------------------------------------------------------------

extern "C" void kernel_launch(void* const* d_in, const int* in_sizes, int n_in,
                              void* d_out, int out_size)
{
    const float* x     = (const float*)d_in[0];
    const int*   mask  = (const int*)  d_in[1];
    const float* W_qkv = (const float*)d_in[2];
    const float* b_qkv = (const float*)d_in[3];
    const float* W_out = (const float*)d_in[4];
    const float* b_out = (const float*)d_in[5];
    float* out = (float*)d_out;

    cudaFuncSetAttribute(gemm_f16x1<0>, cudaFuncAttributeMaxDynamicSharedMemorySize, GEMM_SMEM);
    cudaFuncSetAttribute(gemm_f16x1<1>, cudaFuncAttributeMaxDynamicSharedMemorySize, GEMM_SMEM);
    cudaFuncSetAttribute(attn_mma_kernel, cudaFuncAttributeMaxDynamicSharedMemorySize, ATTN_SMEM);

    uint32_t *xh, *wqh, *oh, *woh;
    cudaGetSymbolAddress((void**)&xh,  g_xh);
    cudaGetSymbolAddress((void**)&wqh, g_wqh);
    cudaGetSymbolAddress((void**)&oh,  g_oh);
    cudaGetSymbolAddress((void**)&woh, g_woh);

    // Operand prep (fragment-packed)
    conv_A_pack<<<(256*64*32)/256, 256>>>(x, xh);
    split_B_pack<<<(64*4*3072)/256, 256>>>(W_qkv, wqh, 3072);
    maskpack<<<(2*2048*64)/256, 256>>>(mask);

    // QKV projection -> Q (gather layout) / K,V (fragment-packed)
    gemm_f16x1<0><<<dim3(24, 32), 256, GEMM_SMEM>>>(xh, wqh, b_qkv, nullptr, 3072);

    // Attention -> g_oh (A-packed)
    attn_mma_kernel<<<dim3(16, 32), 256, ATTN_SMEM>>>();

    // Output projection
    split_B_pack<<<(64*4*1024)/256, 256>>>(W_out, woh, 1024);
    gemm_f16x1<1><<<dim3(8, 32), 256, GEMM_SMEM>>>(oh, woh, b_out, out, 1024);
}

// round 15
// speedup vs baseline: 2.6941x; 1.0177x over previous
#include <cuda_runtime.h>
#include <cuda_fp16.h>
#include <cstdint>

#define SCALE2_ 0.1803368801111204f   // 0.125 * log2(e)

// Fragment-packed f16 operands.
__device__ uint32_t g_xh [4096/16*64*32*4];   // X packed     (= 4096*512)
__device__ uint32_t g_wqh[64*3072*8];         // Wqkv packed  (= 512*3072)
__device__ uint32_t g_oh [4096/16*64*32*4];   // attnO packed
__device__ uint32_t g_woh[64*1024*8];         // Wout packed

// attention operands
__device__ uint32_t g_qh [32*2048*32];        // Q [bh][l][dk2]
__device__ uint32_t g_kh [32*4*2048*8];       // K packed: [bh][t(4)][key(2048)][c(4)][2]
__device__ uint32_t g_vh [32*32*4*64*8];      // V packed: [bh][T(32)][tp(4)][dk(64)][c(4)][2]
__device__ uint32_t g_mb [2*2048*64];         // mask bits

// ---------------------------------------------------------------------------
// Helpers
// ---------------------------------------------------------------------------
__device__ __forceinline__ uint32_t pack_h2(float a, float b) {
    __half2 h = __floats2half2_rn(a, b);
    return *reinterpret_cast<uint32_t*>(&h);
}
__device__ __forceinline__ uint16_t f16bits(float a) {
    __half h = __float2half_rn(a);
    return *reinterpret_cast<uint16_t*>(&h);
}
__device__ __forceinline__ void cp16(uint32_t saddr, const void* gptr) {
    asm volatile("cp.async.cg.shared.global [%0], [%1], 16;\n" :: "r"(saddr), "l"(gptr));
}
__device__ __forceinline__ void cp_commit() {
    asm volatile("cp.async.commit_group;\n" ::: "memory");
}
__device__ __forceinline__ void mma_f16(float* c, const uint32_t* a, const uint32_t* b) {
    asm volatile(
        "mma.sync.aligned.m16n8k16.row.col.f32.f16.f16.f32 "
        "{%0,%1,%2,%3}, {%4,%5,%6,%7}, {%8,%9}, {%0,%1,%2,%3};\n"
        : "+f"(c[0]), "+f"(c[1]), "+f"(c[2]), "+f"(c[3])
        : "r"(a[0]), "r"(a[1]), "r"(a[2]), "r"(a[3]), "r"(b[0]), "r"(b[1]));
}

// V u16 index: value at (key l, dk d) in packed V
__device__ __forceinline__ size_t vidx16(int bh, int l, int d) {
    const int l2 = l >> 1, p = l & 1;
    const int T = l2 >> 5, rem = l2 & 31;
    const int tp = rem >> 3, cr = rem & 7;
    size_t u = (((size_t)(bh*32 + T)*4 + tp)*64 + d)*8 + (cr & 3)*2 + (cr >> 2);
    return u*2 + p;
}

// ---------------------------------------------------------------------------
// Fused operand prep: blockIdx ranges select the job.
//   [0, 2048)          conv_A_pack   (x -> g_xh)
//   [2048, 5120)       split_B_pack  (W_qkv -> g_wqh, N=3072)
//   [5120, 6144)       split_B_pack  (W_out -> g_woh, N=1024)
//   [6144, 7168)       maskpack
// ---------------------------------------------------------------------------
__global__ void prep_all(const float* __restrict__ x,
                         const float* __restrict__ wq,
                         const float* __restrict__ wo,
                         const int*   __restrict__ mask)
{
    const int bidx = blockIdx.x;
    const int tid  = threadIdx.x;
    if (bidx < 2048) {
        // conv_A_pack: one thread per (mb, kc, lane)
        const int i  = bidx * 256 + tid;
        const int l  = i & 31;
        const int kc = (i >> 5) & 63;
        const int mb = i >> 11;
        const int rq = l >> 2, c = l & 3;
        const float2* x2 = (const float2*)x;
        const size_t row0 = (size_t)(mb*16 + rq) * 512;
        const size_t row1 = row0 + 8*512;
        float2 a0 = x2[row0 + kc*8 + c];
        float2 a1 = x2[row1 + kc*8 + c];
        float2 a2 = x2[row0 + kc*8 + c + 4];
        float2 a3 = x2[row1 + kc*8 + c + 4];
        uint4 v;
        v.x = pack_h2(a0.x, a0.y);
        v.y = pack_h2(a1.x, a1.y);
        v.z = pack_h2(a2.x, a2.y);
        v.w = pack_h2(a3.x, a3.y);
        ((uint4*)g_xh)[i] = v;
    } else if (bidx < 6144) {
        const int isWq = (bidx < 5120);
        const int N    = isWq ? 3072 : 1024;
        const float* in = isWq ? wq : wo;
        uint32_t* outp  = isWq ? g_wqh : g_woh;
        const int i = (bidx - (isWq ? 2048 : 5120)) * 256 + tid;
        const int n  = i % N;
        const int c  = (i / N) & 3;
        const int kc = i / (4*N);
        const int k2a = kc*8 + c;
        const int k2b = k2a + 4;
        uint2 v;
        v.x = pack_h2(in[(size_t)(2*k2a)*N + n], in[(size_t)(2*k2a+1)*N + n]);
        v.y = pack_h2(in[(size_t)(2*k2b)*N + n], in[(size_t)(2*k2b+1)*N + n]);
        ((uint2*)outp)[((size_t)kc*N + n)*4 + c] = v;
    } else {
        const int idx = (bidx - 6144) * 256 + tid;
        const int w   = idx & 63;
        const int row = idx >> 6;
        const int4* p = (const int4*)(mask + (size_t)row * 2048 + w * 32);
        uint32_t bits = 0;
#pragma unroll
        for (int i = 0; i < 8; i++) {
            int4 v = p[i];
            bits |= (uint32_t)(v.x != 0) << (4*i)
                 |  (uint32_t)(v.y != 0) << (4*i+1)
                 |  (uint32_t)(v.z != 0) << (4*i+2)
                 |  (uint32_t)(v.w != 0) << (4*i+3);
        }
        g_mb[idx] = bits;
    }
}

// ---------------------------------------------------------------------------
// f16 single-pass GEMM, fragment-packed operands (R14-validated).
// ---------------------------------------------------------------------------
#define OA  0
#define OB  2048
#define STG 4096
#define GEMM_SMEM (2*STG*4)   // 32768 B

template<int EPI>
__global__ void __launch_bounds__(256, 2)
gemm_f16x1(const uint32_t* __restrict__ Ah,
           const uint32_t* __restrict__ Bh,
           const float* __restrict__ bias, float* __restrict__ outp, int N)
{
    extern __shared__ uint32_t sm[];
    const int tid  = threadIdx.x;
    const int lane = tid & 31;
    const int wid  = tid >> 5;
    const int wm   = wid >> 2;
    const int wn   = wid & 3;
    const int rq   = lane >> 2;
    const int cL   = lane & 3;
    const int m0   = blockIdx.y * 128;
    const int n0   = blockIdx.x * 128;
    const int mb0  = m0 >> 4;

    const uint32_t sbase = (uint32_t)__cvta_generic_to_shared(sm);

    float C[4][4][4];
#pragma unroll
    for (int mt = 0; mt < 4; mt++)
#pragma unroll
        for (int nt = 0; nt < 4; nt++)
#pragma unroll
            for (int e = 0; e < 4; e++) C[mt][nt][e] = 0.f;

    auto load_stage = [&](int s, int t) {
        const uint32_t sa = sbase + (uint32_t)(s * STG) * 4;
        const int kc0 = 2*t;
#pragma unroll
        for (int it = 0; it < 2; it++) {
            const int j = it*256 + tid;
            const int mbL = j >> 6, kcL = (j >> 5) & 1, l = j & 31;
            cp16(sa + (OA + j*4)*4,
                 Ah + ((size_t)(mb0 + mbL)*64 + kc0 + kcL)*128 + l*4);
        }
#pragma unroll
        for (int it = 0; it < 2; it++) {
            const int j = it*256 + tid;
            const int kcL = j >> 8, nLoc = (j >> 1) & 127, q = j & 1;
            cp16(sa + (OB + (kcL*128 + nLoc)*8 + q*4)*4,
                 Bh + ((size_t)(kc0 + kcL)*N + n0 + nLoc)*8 + q*4);
        }
        cp_commit();
    };

    load_stage(0, 0);

    const int T = 32;
    for (int t = 0; t < T; t++) {
        if (t + 1 < T) { load_stage((t+1)&1, t+1); }
        if (t + 1 < T) asm volatile("cp.async.wait_group 1;\n" ::: "memory");
        else           asm volatile("cp.async.wait_group 0;\n" ::: "memory");
        __syncthreads();

        const uint32_t* S = sm + (t & 1) * STG;
#pragma unroll
        for (int ss = 0; ss < 2; ss++) {
            uint4 av[4];
#pragma unroll
            for (int mt = 0; mt < 4; mt++)
                av[mt] = *(const uint4*)&S[OA + (((wm*4 + mt)*2 + ss)*32 + lane)*4];
            uint2 bv[4];
#pragma unroll
            for (int nt = 0; nt < 4; nt++)
                bv[nt] = *(const uint2*)&S[OB + ((ss*128 + wn*32 + nt*8 + rq)*4 + cL)*2];
#pragma unroll
            for (int mt = 0; mt < 4; mt++)
#pragma unroll
                for (int nt = 0; nt < 4; nt++)
                    mma_f16(C[mt][nt], (const uint32_t*)&av[mt], (const uint32_t*)&bv[nt]);
        }
        __syncthreads();
    }

    // Epilogue
#pragma unroll
    for (int mt = 0; mt < 4; mt++) {
#pragma unroll
        for (int nt = 0; nt < 4; nt++) {
            const int r = m0 + wm*64 + mt*16 + rq;
            const int c = n0 + wn*32 + nt*8 + cL*2;
            const float b0 = bias[c], b1 = bias[c+1];
            const float v00 = C[mt][nt][0]+b0, v01 = C[mt][nt][1]+b1;
            const float v10 = C[mt][nt][2]+b0, v11 = C[mt][nt][3]+b1;
            if (EPI == 0) {
                const int part = c >> 10;
                const int d0  = c & 1023;
                const int h   = d0 >> 6;
                const int d   = d0 & 63;
                const int dk2 = d >> 1;
                const int bI  = r >> 11;
                const int l   = r & 2047;
                const int bh  = bI*16 + h;
                if (part == 0) {
                    size_t i0 = ((size_t)bh*2048 + l)*32 + dk2;
                    g_qh[i0]        = pack_h2(v00, v01);
                    g_qh[i0 + 8*32] = pack_h2(v10, v11);
                } else if (part == 1) {
                    const int tK = dk2 >> 3, cc = dk2 & 7;
                    size_t ki = ((size_t)(bh*4 + tK)*2048 + l)*8 + (cc & 3)*2 + (cc >> 2);
                    g_kh[ki]      = pack_h2(v00, v01);
                    g_kh[ki + 64] = pack_h2(v10, v11);
                } else {
                    uint16_t* V16 = (uint16_t*)g_vh;
                    size_t i0 = vidx16(bh, l, d);
                    size_t i1 = vidx16(bh, l + 8, d);
                    V16[i0]      = f16bits(v00);
                    V16[i0 + 16] = f16bits(v01);
                    V16[i1]      = f16bits(v10);
                    V16[i1 + 16] = f16bits(v11);
                }
            } else {
                *(float2*)&outp[(size_t)r*N + c]     = make_float2(v00, v01);
                *(float2*)&outp[(size_t)(r+8)*N + c] = make_float2(v10, v11);
            }
        }
    }
}

// ---------------------------------------------------------------------------
// f16 single-pass flash attention, fragment-packed K/V, log2-domain softmax.
// ---------------------------------------------------------------------------
#define AKH 0
#define AVH 2048
#define ASTG 4096
#define ATTN_SMEM (2*ASTG*4)   // 32768 bytes

__device__ __forceinline__ void softmax_row(float (&sC)[8][4], float (&oC)[8][4],
                                            int e0, uint32_t w0, uint32_t w1,
                                            int c, float& mi, float& li)
{
    float rm = -1e30f;
    uint32_t rbits = 0;
#pragma unroll
    for (int j = 0; j < 8; j++) {
        const uint32_t w = (j < 4) ? w0 : w1;
#pragma unroll
        for (int e = 0; e < 2; e++) {
            const int col = 8*j + 2*c + e;
            const uint32_t bit = (w >> (col & 31)) & 1u;
            const float sv = bit ? sC[j][e0+e]*SCALE2_ : 0.f;   // log2 domain
            sC[j][e0+e] = sv;
            rbits |= bit << (2*j + e);
            rm = fmaxf(rm, sv);
        }
    }
    rm = fmaxf(rm, __shfl_xor_sync(0xffffffffu, rm, 1));
    rm = fmaxf(rm, __shfl_xor_sync(0xffffffffu, rm, 2));
    const float mn   = fmaxf(mi, rm);
    const bool  same = (mn == mi);
    float rs = 0.f;
#pragma unroll
    for (int j = 0; j < 8; j++)
#pragma unroll
        for (int e = 0; e < 2; e++) {
            const float pd = exp2f(sC[j][e0+e] - mn);
            rs += pd;
            sC[j][e0+e] = ((rbits >> (2*j + e)) & 1u) ? pd : 0.f;
        }
    rs += __shfl_xor_sync(0xffffffffu, rs, 1);
    rs += __shfl_xor_sync(0xffffffffu, rs, 2);
    if (same) {
        li += rs;
    } else {
        const float fac = exp2f(mi - mn);
        li = li*fac + rs;
        mi = mn;
#pragma unroll
        for (int j = 0; j < 8; j++) { oC[j][e0] *= fac; oC[j][e0+1] *= fac; }
    }
}

__global__ void __launch_bounds__(256, 2)
attn_mma_kernel()
{
    extern __shared__ uint32_t sm[];
    const int tid  = threadIdx.x;
    const int lane = tid & 31;
    const int wid  = tid >> 5;
    const int c    = lane & 3;
    const int rq   = lane >> 2;
    const int bh   = blockIdx.y;
    const int b    = bh >> 4;
    const int h    = bh & 15;
    const int q0   = blockIdx.x * 128;
    const int r0   = q0 + wid*16 + rq;

    const uint32_t sbase = (uint32_t)__cvta_generic_to_shared(sm);

    uint32_t qh[4][4];
    {
        const uint32_t* Qh = g_qh + (size_t)bh*2048*32;
#pragma unroll
        for (int t = 0; t < 4; t++) {
            qh[t][0] = Qh[(size_t)r0*32     + 8*t + c];
            qh[t][1] = Qh[(size_t)(r0+8)*32 + 8*t + c];
            qh[t][2] = Qh[(size_t)r0*32     + 8*t + c + 4];
            qh[t][3] = Qh[(size_t)(r0+8)*32 + 8*t + c + 4];
        }
    }

    float oC[8][4];
#pragma unroll
    for (int j = 0; j < 8; j++)
#pragma unroll
        for (int e = 0; e < 4; e++) oC[j][e] = 0.f;
    float mi[2] = {-1e30f, -1e30f};
    float li[2] = {0.f, 0.f};

    auto load_stage = [&](int s, int k0) {
        const uint32_t sa = sbase + (uint32_t)(s * ASTG) * 4;
        const int T = k0 >> 6;
#pragma unroll
        for (int it = 0; it < 2; it++) {
            const int j = it*256 + tid;
            const int t = j >> 7, keyL = (j >> 1) & 63, q = j & 1;
            cp16(sa + (AKH + t*512 + keyL*8 + q*4)*4,
                 g_kh + ((size_t)(bh*4 + t)*2048 + k0 + keyL)*8 + q*4);
        }
#pragma unroll
        for (int it = 0; it < 2; it++) {
            const int j = it*256 + tid;
            const int tp = j >> 7, dk = (j >> 1) & 63, q = j & 1;
            cp16(sa + (AVH + tp*512 + dk*8 + q*4)*4,
                 g_vh + (((size_t)(bh*32 + T)*4 + tp)*64 + dk)*8 + q*4);
        }
    };

    load_stage(0, 0);
    cp_commit();

    const uint32_t* MB = g_mb + (size_t)b*2048*64;

    for (int t32 = 0; t32 < 32; t32++) {
        const int k0 = t32 * 64;
        if (t32 + 1 < 32) { load_stage((t32+1)&1, k0 + 64); cp_commit(); }
        if (t32 + 1 < 32) asm volatile("cp.async.wait_group 1;\n" ::: "memory");
        else              asm volatile("cp.async.wait_group 0;\n" ::: "memory");
        __syncthreads();

        const uint32_t* S = sm + (t32 & 1) * ASTG;

        float sC[8][4];
#pragma unroll
        for (int j = 0; j < 8; j++)
#pragma unroll
            for (int e = 0; e < 4; e++) sC[j][e] = 0.f;

        // ---- S = Q @ K^T ----
#pragma unroll
        for (int t = 0; t < 4; t++) {
#pragma unroll
            for (int jj = 0; jj < 4; jj++) {
                const int j0 = 2*jj, j1 = 2*jj + 1;
                uint2 B0 = *(const uint2*)&S[AKH + ((t*64 + 8*j0 + rq)*4 + c)*2];
                uint2 B1 = *(const uint2*)&S[AKH + ((t*64 + 8*j1 + rq)*4 + c)*2];
                mma_f16(sC[j0], qh[t], (const uint32_t*)&B0);
                mma_f16(sC[j1], qh[t], (const uint32_t*)&B1);
            }
        }

        const int wbase = k0 >> 5;
        const uint32_t w00 = MB[(size_t)r0*64 + wbase],     w01 = MB[(size_t)r0*64 + wbase + 1];
        const uint32_t w10 = MB[(size_t)(r0+8)*64 + wbase], w11 = MB[(size_t)(r0+8)*64 + wbase + 1];
        softmax_row(sC, oC, 0, w00, w01, c, mi[0], li[0]);
        softmax_row(sC, oC, 2, w10, w11, c, mi[1], li[1]);

        // ---- O += P @ V ----
#pragma unroll
        for (int tp = 0; tp < 4; tp++) {
            uint32_t pah[4];
            pah[0] = pack_h2(sC[2*tp][0],   sC[2*tp][1]);
            pah[1] = pack_h2(sC[2*tp][2],   sC[2*tp][3]);
            pah[2] = pack_h2(sC[2*tp+1][0], sC[2*tp+1][1]);
            pah[3] = pack_h2(sC[2*tp+1][2], sC[2*tp+1][3]);
#pragma unroll
            for (int jj = 0; jj < 4; jj++) {
                const int j0 = 2*jj, j1 = 2*jj + 1;
                uint2 B0 = *(const uint2*)&S[AVH + ((tp*64 + 8*j0 + rq)*4 + c)*2];
                uint2 B1 = *(const uint2*)&S[AVH + ((tp*64 + 8*j1 + rq)*4 + c)*2];
                mma_f16(oC[j0], pah, (const uint32_t*)&B0);
                mma_f16(oC[j1], pah, (const uint32_t*)&B1);
            }
        }
        __syncthreads();
    }

    // normalize + emit out-proj A operand in A-packed layout
    const float inv0 = 1.0f / li[0];
    const float inv1 = 1.0f / li[1];
    const size_t mrow = (size_t)b*2048 + r0;
    const size_t mb = mrow >> 4;
#pragma unroll
    for (int j = 0; j < 8; j++) {
        const int kc = h*4 + (j >> 1);
        const size_t base = ((mb*64 + kc)*32 + rq*4 + c)*4 + (j & 1)*2;
        g_oh[base]     = pack_h2(oC[j][0]*inv0, oC[j][1]*inv0);
        g_oh[base + 1] = pack_h2(oC[j][2]*inv1, oC[j][3]*inv1);
    }
}

// ---------------------------------------------------------------------------

extern "C" void kernel_launch(void* const* d_in, const int* in_sizes, int n_in,
                              void* d_out, int out_size)
{
    const float* x     = (const float*)d_in[0];
    const int*   mask  = (const int*)  d_in[1];
    const float* W_qkv = (const float*)d_in[2];
    const float* b_qkv = (const float*)d_in[3];
    const float* W_out = (const float*)d_in[4];
    const float* b_out = (const float*)d_in[5];
    float* out = (float*)d_out;

    cudaFuncSetAttribute(gemm_f16x1<0>, cudaFuncAttributeMaxDynamicSharedMemorySize, GEMM_SMEM);
    cudaFuncSetAttribute(gemm_f16x1<1>, cudaFuncAttributeMaxDynamicSharedMemorySize, GEMM_SMEM);
    cudaFuncSetAttribute(attn_mma_kernel, cudaFuncAttributeMaxDynamicSharedMemorySize, ATTN_SMEM);

    uint32_t *xh, *wqh, *oh, *woh;
    cudaGetSymbolAddress((void**)&xh,  g_xh);
    cudaGetSymbolAddress((void**)&wqh, g_wqh);
    cudaGetSymbolAddress((void**)&oh,  g_oh);
    cudaGetSymbolAddress((void**)&woh, g_woh);

    // Fused operand prep (A-pack + both W-packs + maskpack in one launch)
    prep_all<<<7168, 256>>>(x, W_qkv, W_out, mask);

    // QKV projection -> Q / K / V (fragment-packed)
    gemm_f16x1<0><<<dim3(24, 32), 256, GEMM_SMEM>>>(xh, wqh, b_qkv, nullptr, 3072);

    // Attention -> g_oh (A-packed)
    attn_mma_kernel<<<dim3(16, 32), 256, ATTN_SMEM>>>();

    // Output projection
    gemm_f16x1<1><<<dim3(8, 32), 256, GEMM_SMEM>>>(oh, woh, b_out, out, 1024);
}

// round 17
// speedup vs baseline: 2.7262x; 1.0119x over previous
#include <cuda_runtime.h>
#include <cuda_fp16.h>
#include <cstdint>

#define SCALE2_ 0.1803368801111204f   // 0.125 * log2(e)

// Fragment-packed f16 operands.
__device__ uint32_t g_xh [4096/16*64*32*4];   // X packed     (= 4096*512)
__device__ uint32_t g_wqh[64*3072*8];         // Wqkv packed  (= 512*3072)
__device__ uint32_t g_oh [4096/16*64*32*4];   // attnO packed
__device__ uint32_t g_woh[64*1024*8];         // Wout packed

// attention operands
__device__ uint32_t g_qh [32*2048*32];        // Q [bh][l][dk2]
__device__ uint32_t g_kh [32*4*2048*8];       // K packed: [bh][t(4)][key(2048)][c(4)][2]
__device__ uint32_t g_vh [32*32*4*64*8];      // V packed: [bh][T(32)][tp(4)][dk(64)][c(4)][2]
__device__ uint32_t g_mb [2*2048*64];         // mask bits

// ---------------------------------------------------------------------------
// Helpers
// ---------------------------------------------------------------------------
__device__ __forceinline__ uint32_t pack_h2(float a, float b) {
    __half2 h = __floats2half2_rn(a, b);
    return *reinterpret_cast<uint32_t*>(&h);
}
__device__ __forceinline__ uint16_t f16bits(float a) {
    __half h = __float2half_rn(a);
    return *reinterpret_cast<uint16_t*>(&h);
}
__device__ __forceinline__ void cp16(uint32_t saddr, const void* gptr) {
    asm volatile("cp.async.cg.shared.global [%0], [%1], 16;\n" :: "r"(saddr), "l"(gptr));
}
__device__ __forceinline__ void cp_commit() {
    asm volatile("cp.async.commit_group;\n" ::: "memory");
}
__device__ __forceinline__ void mma_f16(float* c, const uint32_t* a, const uint32_t* b) {
    asm volatile(
        "mma.sync.aligned.m16n8k16.row.col.f32.f16.f16.f32 "
        "{%0,%1,%2,%3}, {%4,%5,%6,%7}, {%8,%9}, {%0,%1,%2,%3};\n"
        : "+f"(c[0]), "+f"(c[1]), "+f"(c[2]), "+f"(c[3])
        : "r"(a[0]), "r"(a[1]), "r"(a[2]), "r"(a[3]), "r"(b[0]), "r"(b[1]));
}

// V u16 index: value at (key l, dk d) in packed V
__device__ __forceinline__ size_t vidx16(int bh, int l, int d) {
    const int l2 = l >> 1, p = l & 1;
    const int T = l2 >> 5, rem = l2 & 31;
    const int tp = rem >> 3, cr = rem & 7;
    size_t u = (((size_t)(bh*32 + T)*4 + tp)*64 + d)*8 + (cr & 3)*2 + (cr >> 2);
    return u*2 + p;
}

// ---------------------------------------------------------------------------
// Fused operand prep (R15-validated)
// ---------------------------------------------------------------------------
__global__ void prep_all(const float* __restrict__ x,
                         const float* __restrict__ wq,
                         const float* __restrict__ wo,
                         const int*   __restrict__ mask)
{
    const int bidx = blockIdx.x;
    const int tid  = threadIdx.x;
    if (bidx < 2048) {
        const int i  = bidx * 256 + tid;
        const int l  = i & 31;
        const int kc = (i >> 5) & 63;
        const int mb = i >> 11;
        const int rq = l >> 2, c = l & 3;
        const float2* x2 = (const float2*)x;
        const size_t row0 = (size_t)(mb*16 + rq) * 512;
        const size_t row1 = row0 + 8*512;
        float2 a0 = x2[row0 + kc*8 + c];
        float2 a1 = x2[row1 + kc*8 + c];
        float2 a2 = x2[row0 + kc*8 + c + 4];
        float2 a3 = x2[row1 + kc*8 + c + 4];
        uint4 v;
        v.x = pack_h2(a0.x, a0.y);
        v.y = pack_h2(a1.x, a1.y);
        v.z = pack_h2(a2.x, a2.y);
        v.w = pack_h2(a3.x, a3.y);
        ((uint4*)g_xh)[i] = v;
    } else if (bidx < 6144) {
        const int isWq = (bidx < 5120);
        const int N    = isWq ? 3072 : 1024;
        const float* in = isWq ? wq : wo;
        uint32_t* outp  = isWq ? g_wqh : g_woh;
        const int i = (bidx - (isWq ? 2048 : 5120)) * 256 + tid;
        const int n  = i % N;
        const int c  = (i / N) & 3;
        const int kc = i / (4*N);
        const int k2a = kc*8 + c;
        const int k2b = k2a + 4;
        uint2 v;
        v.x = pack_h2(in[(size_t)(2*k2a)*N + n], in[(size_t)(2*k2a+1)*N + n]);
        v.y = pack_h2(in[(size_t)(2*k2b)*N + n], in[(size_t)(2*k2b+1)*N + n]);
        ((uint2*)outp)[((size_t)kc*N + n)*4 + c] = v;
    } else {
        const int idx = (bidx - 6144) * 256 + tid;
        const int w   = idx & 63;
        const int row = idx >> 6;
        const int4* p = (const int4*)(mask + (size_t)row * 2048 + w * 32);
        uint32_t bits = 0;
#pragma unroll
        for (int i = 0; i < 8; i++) {
            int4 v = p[i];
            bits |= (uint32_t)(v.x != 0) << (4*i)
                 |  (uint32_t)(v.y != 0) << (4*i+1)
                 |  (uint32_t)(v.z != 0) << (4*i+2)
                 |  (uint32_t)(v.w != 0) << (4*i+3);
        }
        g_mb[idx] = bits;
    }
}

// ---------------------------------------------------------------------------
// f16 single-pass GEMM, fragment-packed operands, 3-stage pipeline.
// Handshake per tile t:  wait(own group t) -> __syncthreads (publish + close
// iter t-1 reads) -> issue tile t+2 -> compute stage t%3.
// ---------------------------------------------------------------------------
#define OA  0
#define OB  2048
#define STG 4096
#define GEMM_SMEM (3*STG*4)   // 49152 B

template<int EPI>
__global__ void __launch_bounds__(256, 2)
gemm_f16x1(const uint32_t* __restrict__ Ah,
           const uint32_t* __restrict__ Bh,
           const float* __restrict__ bias, float* __restrict__ outp, int N)
{
    extern __shared__ uint32_t sm[];
    const int tid  = threadIdx.x;
    const int lane = tid & 31;
    const int wid  = tid >> 5;
    const int wm   = wid >> 2;
    const int wn   = wid & 3;
    const int rq   = lane >> 2;
    const int cL   = lane & 3;
    const int m0   = blockIdx.y * 128;
    const int n0   = blockIdx.x * 128;
    const int mb0  = m0 >> 4;

    const uint32_t sbase = (uint32_t)__cvta_generic_to_shared(sm);

    float C[4][4][4];
#pragma unroll
    for (int mt = 0; mt < 4; mt++)
#pragma unroll
        for (int nt = 0; nt < 4; nt++)
#pragma unroll
            for (int e = 0; e < 4; e++) C[mt][nt][e] = 0.f;

    auto load_stage = [&](int s, int t) {
        const uint32_t sa = sbase + (uint32_t)(s * STG) * 4;
        const int kc0 = 2*t;
#pragma unroll
        for (int it = 0; it < 2; it++) {
            const int j = it*256 + tid;
            const int mbL = j >> 6, kcL = (j >> 5) & 1, l = j & 31;
            cp16(sa + (OA + j*4)*4,
                 Ah + ((size_t)(mb0 + mbL)*64 + kc0 + kcL)*128 + l*4);
        }
#pragma unroll
        for (int it = 0; it < 2; it++) {
            const int j = it*256 + tid;
            const int kcL = j >> 8, nLoc = (j >> 1) & 127, q = j & 1;
            cp16(sa + (OB + (kcL*128 + nLoc)*8 + q*4)*4,
                 Bh + ((size_t)(kc0 + kcL)*N + n0 + nLoc)*8 + q*4);
        }
        cp_commit();
    };

    load_stage(0, 0);
    load_stage(1, 1);

    const int T = 32;
    for (int t = 0; t < T; t++) {
        if (t < T-1) asm volatile("cp.async.wait_group 1;\n" ::: "memory");
        else         asm volatile("cp.async.wait_group 0;\n" ::: "memory");
        __syncthreads();
        if (t + 2 < T) load_stage((t+2) % 3, t+2);

        const uint32_t* S = sm + (t % 3) * STG;
#pragma unroll
        for (int ss = 0; ss < 2; ss++) {
            uint4 av[4];
#pragma unroll
            for (int mt = 0; mt < 4; mt++)
                av[mt] = *(const uint4*)&S[OA + (((wm*4 + mt)*2 + ss)*32 + lane)*4];
            uint2 bv[4];
#pragma unroll
            for (int nt = 0; nt < 4; nt++)
                bv[nt] = *(const uint2*)&S[OB + ((ss*128 + wn*32 + nt*8 + rq)*4 + cL)*2];
#pragma unroll
            for (int mt = 0; mt < 4; mt++)
#pragma unroll
                for (int nt = 0; nt < 4; nt++)
                    mma_f16(C[mt][nt], (const uint32_t*)&av[mt], (const uint32_t*)&bv[nt]);
        }
    }

    // Epilogue
#pragma unroll
    for (int mt = 0; mt < 4; mt++) {
#pragma unroll
        for (int nt = 0; nt < 4; nt++) {
            const int r = m0 + wm*64 + mt*16 + rq;
            const int c = n0 + wn*32 + nt*8 + cL*2;
            const float b0 = bias[c], b1 = bias[c+1];
            const float v00 = C[mt][nt][0]+b0, v01 = C[mt][nt][1]+b1;
            const float v10 = C[mt][nt][2]+b0, v11 = C[mt][nt][3]+b1;
            if (EPI == 0) {
                const int part = c >> 10;
                const int d0  = c & 1023;
                const int h   = d0 >> 6;
                const int d   = d0 & 63;
                const int dk2 = d >> 1;
                const int bI  = r >> 11;
                const int l   = r & 2047;
                const int bh  = bI*16 + h;
                if (part == 0) {
                    size_t i0 = ((size_t)bh*2048 + l)*32 + dk2;
                    g_qh[i0]        = pack_h2(v00, v01);
                    g_qh[i0 + 8*32] = pack_h2(v10, v11);
                } else if (part == 1) {
                    const int tK = dk2 >> 3, cc = dk2 & 7;
                    size_t ki = ((size_t)(bh*4 + tK)*2048 + l)*8 + (cc & 3)*2 + (cc >> 2);
                    g_kh[ki]      = pack_h2(v00, v01);
                    g_kh[ki + 64] = pack_h2(v10, v11);
                } else {
                    uint16_t* V16 = (uint16_t*)g_vh;
                    size_t i0 = vidx16(bh, l, d);
                    size_t i1 = vidx16(bh, l + 8, d);
                    V16[i0]      = f16bits(v00);
                    V16[i0 + 16] = f16bits(v01);
                    V16[i1]      = f16bits(v10);
                    V16[i1 + 16] = f16bits(v11);
                }
            } else {
                *(float2*)&outp[(size_t)r*N + c]     = make_float2(v00, v01);
                *(float2*)&outp[(size_t)(r+8)*N + c] = make_float2(v10, v11);
            }
        }
    }
}

// ---------------------------------------------------------------------------
// f16 single-pass flash attention, fragment-packed K/V, log2 softmax,
// 3-stage pipeline with the corrected handshake.
// ---------------------------------------------------------------------------
#define AKH 0
#define AVH 2048
#define ASTG 4096
#define ATTN_SMEM (3*ASTG*4)   // 49152 bytes

__device__ __forceinline__ void softmax_row(float (&sC)[8][4], float (&oC)[8][4],
                                            int e0, uint32_t w0, uint32_t w1,
                                            int c, float& mi, float& li)
{
    float rm = -1e30f;
    uint32_t rbits = 0;
#pragma unroll
    for (int j = 0; j < 8; j++) {
        const uint32_t w = (j < 4) ? w0 : w1;
#pragma unroll
        for (int e = 0; e < 2; e++) {
            const int col = 8*j + 2*c + e;
            const uint32_t bit = (w >> (col & 31)) & 1u;
            const float sv = bit ? sC[j][e0+e]*SCALE2_ : 0.f;   // log2 domain
            sC[j][e0+e] = sv;
            rbits |= bit << (2*j + e);
            rm = fmaxf(rm, sv);
        }
    }
    rm = fmaxf(rm, __shfl_xor_sync(0xffffffffu, rm, 1));
    rm = fmaxf(rm, __shfl_xor_sync(0xffffffffu, rm, 2));
    const float mn   = fmaxf(mi, rm);
    const bool  same = (mn == mi);
    float rs = 0.f;
#pragma unroll
    for (int j = 0; j < 8; j++)
#pragma unroll
        for (int e = 0; e < 2; e++) {
            const float pd = exp2f(sC[j][e0+e] - mn);
            rs += pd;
            sC[j][e0+e] = ((rbits >> (2*j + e)) & 1u) ? pd : 0.f;
        }
    rs += __shfl_xor_sync(0xffffffffu, rs, 1);
    rs += __shfl_xor_sync(0xffffffffu, rs, 2);
    if (same) {
        li += rs;
    } else {
        const float fac = exp2f(mi - mn);
        li = li*fac + rs;
        mi = mn;
#pragma unroll
        for (int j = 0; j < 8; j++) { oC[j][e0] *= fac; oC[j][e0+1] *= fac; }
    }
}

__global__ void __launch_bounds__(256, 2)
attn_mma_kernel()
{
    extern __shared__ uint32_t sm[];
    const int tid  = threadIdx.x;
    const int lane = tid & 31;
    const int wid  = tid >> 5;
    const int c    = lane & 3;
    const int rq   = lane >> 2;
    const int bh   = blockIdx.y;
    const int b    = bh >> 4;
    const int h    = bh & 15;
    const int q0   = blockIdx.x * 128;
    const int r0   = q0 + wid*16 + rq;

    const uint32_t sbase = (uint32_t)__cvta_generic_to_shared(sm);

    uint32_t qh[4][4];
    {
        const uint32_t* Qh = g_qh + (size_t)bh*2048*32;
#pragma unroll
        for (int t = 0; t < 4; t++) {
            qh[t][0] = Qh[(size_t)r0*32     + 8*t + c];
            qh[t][1] = Qh[(size_t)(r0+8)*32 + 8*t + c];
            qh[t][2] = Qh[(size_t)r0*32     + 8*t + c + 4];
            qh[t][3] = Qh[(size_t)(r0+8)*32 + 8*t + c + 4];
        }
    }

    float oC[8][4];
#pragma unroll
    for (int j = 0; j < 8; j++)
#pragma unroll
        for (int e = 0; e < 4; e++) oC[j][e] = 0.f;
    float mi[2] = {-1e30f, -1e30f};
    float li[2] = {0.f, 0.f};

    auto load_stage = [&](int s, int k0) {
        const uint32_t sa = sbase + (uint32_t)(s * ASTG) * 4;
        const int T = k0 >> 6;
#pragma unroll
        for (int it = 0; it < 2; it++) {
            const int j = it*256 + tid;
            const int t = j >> 7, keyL = (j >> 1) & 63, q = j & 1;
            cp16(sa + (AKH + t*512 + keyL*8 + q*4)*4,
                 g_kh + ((size_t)(bh*4 + t)*2048 + k0 + keyL)*8 + q*4);
        }
#pragma unroll
        for (int it = 0; it < 2; it++) {
            const int j = it*256 + tid;
            const int tp = j >> 7, dk = (j >> 1) & 63, q = j & 1;
            cp16(sa + (AVH + tp*512 + dk*8 + q*4)*4,
                 g_vh + (((size_t)(bh*32 + T)*4 + tp)*64 + dk)*8 + q*4);
        }
        cp_commit();
    };

    load_stage(0, 0);
    load_stage(1, 64);

    const uint32_t* MB = g_mb + (size_t)b*2048*64;

    const int NT = 32;
    for (int t32 = 0; t32 < NT; t32++) {
        const int k0 = t32 * 64;
        if (t32 < NT-1) asm volatile("cp.async.wait_group 1;\n" ::: "memory");
        else            asm volatile("cp.async.wait_group 0;\n" ::: "memory");
        __syncthreads();
        if (t32 + 2 < NT) load_stage((t32+2) % 3, k0 + 128);

        const uint32_t* S = sm + (t32 % 3) * ASTG;

        float sC[8][4];
#pragma unroll
        for (int j = 0; j < 8; j++)
#pragma unroll
            for (int e = 0; e < 4; e++) sC[j][e] = 0.f;

        // ---- S = Q @ K^T ----
#pragma unroll
        for (int t = 0; t < 4; t++) {
#pragma unroll
            for (int jj = 0; jj < 4; jj++) {
                const int j0 = 2*jj, j1 = 2*jj + 1;
                uint2 B0 = *(const uint2*)&S[AKH + ((t*64 + 8*j0 + rq)*4 + c)*2];
                uint2 B1 = *(const uint2*)&S[AKH + ((t*64 + 8*j1 + rq)*4 + c)*2];
                mma_f16(sC[j0], qh[t], (const uint32_t*)&B0);
                mma_f16(sC[j1], qh[t], (const uint32_t*)&B1);
            }
        }

        const int wbase = k0 >> 5;
        const uint32_t w00 = MB[(size_t)r0*64 + wbase],     w01 = MB[(size_t)r0*64 + wbase + 1];
        const uint32_t w10 = MB[(size_t)(r0+8)*64 + wbase], w11 = MB[(size_t)(r0+8)*64 + wbase + 1];
        softmax_row(sC, oC, 0, w00, w01, c, mi[0], li[0]);
        softmax_row(sC, oC, 2, w10, w11, c, mi[1], li[1]);

        // ---- O += P @ V ----
#pragma unroll
        for (int tp = 0; tp < 4; tp++) {
            uint32_t pah[4];
            pah[0] = pack_h2(sC[2*tp][0],   sC[2*tp][1]);
            pah[1] = pack_h2(sC[2*tp][2],   sC[2*tp][3]);
            pah[2] = pack_h2(sC[2*tp+1][0], sC[2*tp+1][1]);
            pah[3] = pack_h2(sC[2*tp+1][2], sC[2*tp+1][3]);
#pragma unroll
            for (int jj = 0; jj < 4; jj++) {
                const int j0 = 2*jj, j1 = 2*jj + 1;
                uint2 B0 = *(const uint2*)&S[AVH + ((tp*64 + 8*j0 + rq)*4 + c)*2];
                uint2 B1 = *(const uint2*)&S[AVH + ((tp*64 + 8*j1 + rq)*4 + c)*2];
                mma_f16(oC[j0], pah, (const uint32_t*)&B0);
                mma_f16(oC[j1], pah, (const uint32_t*)&B1);
            }
        }
    }

    // normalize + emit out-proj A operand in A-packed layout
    const float inv0 = 1.0f / li[0];
    const float inv1 = 1.0f / li[1];
    const size_t mrow = (size_t)b*2048 + r0;
    const size_t mb = mrow >> 4;
#pragma unroll
    for (int j = 0; j < 8; j++) {
        const int kc = h*4 + (j >> 1);
        const size_t base = ((mb*64 + kc)*32 + rq*4 + c)*4 + (j & 1)*2;
        g_oh[base]     = pack_h2(oC[j][0]*inv0, oC[j][1]*inv0);
        g_oh[base + 1] = pack_h2(oC[j][2]*inv1, oC[j][3]*inv1);
    }
}

// ---------------------------------------------------------------------------

extern "C" void kernel_launch(void* const* d_in, const int* in_sizes, int n_in,
                              void* d_out, int out_size)
{
    const float* x     = (const float*)d_in[0];
    const int*   mask  = (const int*)  d_in[1];
    const float* W_qkv = (const float*)d_in[2];
    const float* b_qkv = (const float*)d_in[3];
    const float* W_out = (const float*)d_in[4];
    const float* b_out = (const float*)d_in[5];
    float* out = (float*)d_out;

    cudaFuncSetAttribute(gemm_f16x1<0>, cudaFuncAttributeMaxDynamicSharedMemorySize, GEMM_SMEM);
    cudaFuncSetAttribute(gemm_f16x1<1>, cudaFuncAttributeMaxDynamicSharedMemorySize, GEMM_SMEM);
    cudaFuncSetAttribute(attn_mma_kernel, cudaFuncAttributeMaxDynamicSharedMemorySize, ATTN_SMEM);

    uint32_t *xh, *wqh, *oh, *woh;
    cudaGetSymbolAddress((void**)&xh,  g_xh);
    cudaGetSymbolAddress((void**)&wqh, g_wqh);
    cudaGetSymbolAddress((void**)&oh,  g_oh);
    cudaGetSymbolAddress((void**)&woh, g_woh);

    // Fused operand prep
    prep_all<<<7168, 256>>>(x, W_qkv, W_out, mask);

    // QKV projection -> Q / K / V (fragment-packed)
    gemm_f16x1<0><<<dim3(24, 32), 256, GEMM_SMEM>>>(xh, wqh, b_qkv, nullptr, 3072);

    // Attention -> g_oh (A-packed)
    attn_mma_kernel<<<dim3(16, 32), 256, ATTN_SMEM>>>();

    // Output projection
    gemm_f16x1<1><<<dim3(8, 32), 256, GEMM_SMEM>>>(oh, woh, b_out, out, 1024);
}